// round 1
// baseline (speedup 1.0000x reference)
#include <cuda_runtime.h>
#include <cstdint>

#define NN 100000
#define NE 1600000
#define F  128

// ---------------- scratch (device globals: no allocation allowed) ----------
__device__ __align__(16) float g_mean[(size_t)NN * F];   // 51.2 MB
__device__ __align__(16) float g_h1[(size_t)NN * F];     // 51.2 MB
__device__ int g_rowptr[NN + 1];
__device__ int g_fill[NN];
__device__ int g_csr[NE];

// ---------------- CSR build ------------------------------------------------
__global__ void k_zero(int n) {
    int i = blockIdx.x * blockDim.x + threadIdx.x;
    if (i < n) g_rowptr[i] = 0;
}

__global__ void k_hist(const int* __restrict__ dst, int E) {
    int i = blockIdx.x * blockDim.x + threadIdx.x;
    if (i < E) atomicAdd(&g_rowptr[dst[i] + 1], 1);
}

// single-block chunked inclusive scan of g_rowptr[0..n)
__global__ void k_scan(int n) {
    __shared__ int warpsums[32];
    __shared__ int carry;
    int lane = threadIdx.x & 31, wid = threadIdx.x >> 5;
    if (threadIdx.x == 0) carry = 0;
    __syncthreads();
    for (int base = 0; base < n; base += 1024) {
        int i = base + threadIdx.x;
        int v = (i < n) ? g_rowptr[i] : 0;
        int sv = v;
#pragma unroll
        for (int o = 1; o < 32; o <<= 1) {
            int t = __shfl_up_sync(0xffffffffu, sv, o);
            if (lane >= o) sv += t;
        }
        if (lane == 31) warpsums[wid] = sv;
        __syncthreads();
        if (wid == 0) {
            int w = warpsums[lane];
#pragma unroll
            for (int o = 1; o < 32; o <<= 1) {
                int t = __shfl_up_sync(0xffffffffu, w, o);
                if (lane >= o) w += t;
            }
            warpsums[lane] = w;
        }
        __syncthreads();
        int off = (wid > 0) ? warpsums[wid - 1] : 0;
        int incl = sv + off + carry;
        if (i < n) g_rowptr[i] = incl;
        __syncthreads();                    // all warpsums/carry reads done
        if (threadIdx.x == 0) carry += warpsums[31];
        __syncthreads();
    }
}

__global__ void k_fill(int n) {
    int i = blockIdx.x * blockDim.x + threadIdx.x;
    if (i < n) g_fill[i] = g_rowptr[i];
}

__global__ void k_scatter(const int* __restrict__ src, const int* __restrict__ dst, int E) {
    int i = blockIdx.x * blockDim.x + threadIdx.x;
    if (i < E) {
        int pos = atomicAdd(&g_fill[dst[i]], 1);
        g_csr[pos] = src[i];
    }
}

// ---------------- mean aggregation: warp per destination node --------------
// h_in == nullptr -> read g_h1. Writes g_mean. No float atomics anywhere.
__global__ void k_agg(const float* __restrict__ h_in, int M) {
    const float* __restrict__ h = h_in ? h_in : g_h1;
    int node = (blockIdx.x * blockDim.x + threadIdx.x) >> 5;
    if (node >= M) return;
    int lane = threadIdx.x & 31;
    int s0 = g_rowptr[node], s1 = g_rowptr[node + 1];
    float4 acc = make_float4(0.f, 0.f, 0.f, 0.f);
    int i = s0;
    for (; i + 1 < s1; i += 2) {
        int a = g_csr[i], b = g_csr[i + 1];
        float4 v1 = *(const float4*)(h + (size_t)a * F + lane * 4);
        float4 v2 = *(const float4*)(h + (size_t)b * F + lane * 4);
        acc.x += v1.x + v2.x; acc.y += v1.y + v2.y;
        acc.z += v1.z + v2.z; acc.w += v1.w + v2.w;
    }
    if (i < s1) {
        int a = g_csr[i];
        float4 v1 = *(const float4*)(h + (size_t)a * F + lane * 4);
        acc.x += v1.x; acc.y += v1.y; acc.z += v1.z; acc.w += v1.w;
    }
    int deg = s1 - s0;
    float inv = 1.0f / (float)max(deg, 1);
    acc.x *= inv; acc.y *= inv; acc.z *= inv; acc.w *= inv;
    *(float4*)(g_mean + (size_t)node * F + lane * 4) = acc;
}

// ---------------- fused dual-GEMM: out = hs@Ws + mean@Wn + b (+leaky) ------
// BM=64 rows/block, full N=128. 256 threads: tx=tid%32 (4 cols), ty=tid/32 (8 rows).
template <bool LEAKY>
__global__ void __launch_bounds__(256)
k_gemm(const float* __restrict__ hs_in,
       const float* __restrict__ Ws, const float* __restrict__ Wn,
       const float* __restrict__ bias,
       float* __restrict__ out_in, int M) {
    const float* __restrict__ hs = hs_in ? hs_in : g_h1;
    float* __restrict__ out = out_in ? out_in : g_h1;

    __shared__ float AsT[16][68];     // transposed A tile (pad vs conflicts)
    __shared__ float Wt[16][128];

    int tid = threadIdx.x;
    int tx = tid & 31;       // column group: cols tx*4 .. tx*4+3
    int ty = tid >> 5;       // row group:    rows ty*8 .. ty*8+7
    int base = blockIdx.x * 64;

    float4 acc[8];
#pragma unroll
    for (int i = 0; i < 8; i++) acc[i] = make_float4(0.f, 0.f, 0.f, 0.f);

    // A-tile load mapping: r = tid>>2 (0..63), c4 = (tid&3)*4
    int lr = tid >> 2;
    int lc = (tid & 3) * 4;

#pragma unroll
    for (int p = 0; p < 2; p++) {
        const float* __restrict__ A = (p == 0) ? hs : g_mean;
        const float* __restrict__ W = (p == 0) ? Ws : Wn;
#pragma unroll
        for (int kc = 0; kc < F; kc += 16) {
            // load A tile [64 x 16] -> AsT[16][64]
            float4 av = make_float4(0.f, 0.f, 0.f, 0.f);
            int grow = base + lr;
            if (grow < M) av = *(const float4*)(A + (size_t)grow * F + kc + lc);
            AsT[lc + 0][lr] = av.x;
            AsT[lc + 1][lr] = av.y;
            AsT[lc + 2][lr] = av.z;
            AsT[lc + 3][lr] = av.w;
            // load W tile [16 x 128]
#pragma unroll
            for (int j = 0; j < 2; j++) {
                int idx = tid + j * 256;
                int wr = idx >> 5, wc = (idx & 31) * 4;
                *(float4*)&Wt[wr][wc] = *(const float4*)(W + (size_t)(kc + wr) * F + wc);
            }
            __syncthreads();
#pragma unroll
            for (int k = 0; k < 16; k++) {
                float4 bf = *(const float4*)&Wt[k][tx * 4];
                float4 a0 = *(const float4*)&AsT[k][ty * 8];
                float4 a1 = *(const float4*)&AsT[k][ty * 8 + 4];
                acc[0].x += a0.x * bf.x; acc[0].y += a0.x * bf.y; acc[0].z += a0.x * bf.z; acc[0].w += a0.x * bf.w;
                acc[1].x += a0.y * bf.x; acc[1].y += a0.y * bf.y; acc[1].z += a0.y * bf.z; acc[1].w += a0.y * bf.w;
                acc[2].x += a0.z * bf.x; acc[2].y += a0.z * bf.y; acc[2].z += a0.z * bf.z; acc[2].w += a0.z * bf.w;
                acc[3].x += a0.w * bf.x; acc[3].y += a0.w * bf.y; acc[3].z += a0.w * bf.z; acc[3].w += a0.w * bf.w;
                acc[4].x += a1.x * bf.x; acc[4].y += a1.x * bf.y; acc[4].z += a1.x * bf.z; acc[4].w += a1.x * bf.w;
                acc[5].x += a1.y * bf.x; acc[5].y += a1.y * bf.y; acc[5].z += a1.y * bf.z; acc[5].w += a1.y * bf.w;
                acc[6].x += a1.z * bf.x; acc[6].y += a1.z * bf.y; acc[6].z += a1.z * bf.z; acc[6].w += a1.z * bf.w;
                acc[7].x += a1.w * bf.x; acc[7].y += a1.w * bf.y; acc[7].z += a1.w * bf.z; acc[7].w += a1.w * bf.w;
            }
            __syncthreads();
        }
    }

    float4 bb = *(const float4*)(bias + tx * 4);
#pragma unroll
    for (int i = 0; i < 8; i++) {
        int row = base + ty * 8 + i;
        if (row >= M) break;
        float4 v = acc[i];
        v.x += bb.x; v.y += bb.y; v.z += bb.z; v.w += bb.w;
        if (LEAKY) {
            v.x = v.x > 0.f ? v.x : 0.2f * v.x;
            v.y = v.y > 0.f ? v.y : 0.2f * v.y;
            v.z = v.z > 0.f ? v.z : 0.2f * v.z;
            v.w = v.w > 0.f ? v.w : 0.2f * v.w;
        }
        *(float4*)(out + (size_t)row * F + tx * 4) = v;
    }
}

// ---------------- launch ----------------------------------------------------
extern "C" void kernel_launch(void* const* d_in, const int* in_sizes, int n_in,
                              void* d_out, int out_size) {
    const float* emb = (const float*)d_in[0];
    const float* W1s = (const float*)d_in[1];
    const float* W1n = (const float*)d_in[2];
    const float* b1  = (const float*)d_in[3];
    const float* W2s = (const float*)d_in[4];
    const float* W2n = (const float*)d_in[5];
    const float* b2  = (const float*)d_in[6];
    const int*   edg = (const int*)d_in[7];

    int E = in_sizes[7] / 2;
    int M = in_sizes[0] / F;
    const int* src = edg;
    const int* dst = edg + E;
    float* out = (float*)d_out;

    // CSR by destination (once; shared by both layers)
    k_zero<<<(M + 1 + 255) / 256, 256>>>(M + 1);
    k_hist<<<(E + 255) / 256, 256>>>(dst, E);
    k_scan<<<1, 1024>>>(M + 1);
    k_fill<<<(M + 255) / 256, 256>>>(M);
    k_scatter<<<(E + 255) / 256, 256>>>(src, dst, E);

    int aggBlocks = (M * 32 + 255) / 256;
    int gemmBlocks = (M + 63) / 64;

    // layer 1: mean(emb) ; h1 = leaky(emb@W1s + mean@W1n + b1)
    k_agg<<<aggBlocks, 256>>>(emb, M);
    k_gemm<true><<<gemmBlocks, 256>>>(emb, W1s, W1n, b1, nullptr, M);

    // layer 2: mean(h1) ; out = h1@W2s + mean@W2n + b2
    k_agg<<<aggBlocks, 256>>>(nullptr, M);
    k_gemm<false><<<gemmBlocks, 256>>>(nullptr, W2s, W2n, b2, out, M);
}

// round 2
// speedup vs baseline: 1.0057x; 1.0057x over previous
#include <cuda_runtime.h>
#include <cstdint>

#define NN 100000
#define NE 1600000
#define F  128

// ---------------- scratch (device globals: no allocation allowed) ----------
__device__ __align__(16) float g_mean[(size_t)NN * F];   // 51.2 MB
__device__ __align__(16) float g_h1[(size_t)NN * F];     // 51.2 MB
__device__ int g_rowptr[NN + 1];
__device__ int g_fill[NN];
__device__ int g_csr[NE];

// ---------------- CSR build ------------------------------------------------
__global__ void k_zero(int n) {
    int i = blockIdx.x * blockDim.x + threadIdx.x;
    if (i < n) g_rowptr[i] = 0;
}

__global__ void k_hist(const int* __restrict__ dst, int E) {
    int i = blockIdx.x * blockDim.x + threadIdx.x;
    if (i < E) atomicAdd(&g_rowptr[dst[i] + 1], 1);
}

// single-block chunked inclusive scan of g_rowptr[0..n)
__global__ void k_scan(int n) {
    __shared__ int warpsums[32];
    __shared__ int carry;
    int lane = threadIdx.x & 31, wid = threadIdx.x >> 5;
    if (threadIdx.x == 0) carry = 0;
    __syncthreads();
    for (int base = 0; base < n; base += 1024) {
        int i = base + threadIdx.x;
        int v = (i < n) ? g_rowptr[i] : 0;
        int sv = v;
#pragma unroll
        for (int o = 1; o < 32; o <<= 1) {
            int t = __shfl_up_sync(0xffffffffu, sv, o);
            if (lane >= o) sv += t;
        }
        if (lane == 31) warpsums[wid] = sv;
        __syncthreads();
        if (wid == 0) {
            int w = warpsums[lane];
#pragma unroll
            for (int o = 1; o < 32; o <<= 1) {
                int t = __shfl_up_sync(0xffffffffu, w, o);
                if (lane >= o) w += t;
            }
            warpsums[lane] = w;
        }
        __syncthreads();
        int off = (wid > 0) ? warpsums[wid - 1] : 0;
        int incl = sv + off + carry;
        if (i < n) g_rowptr[i] = incl;
        __syncthreads();
        if (threadIdx.x == 0) carry += warpsums[31];
        __syncthreads();
    }
}

__global__ void k_fill(int n) {
    int i = blockIdx.x * blockDim.x + threadIdx.x;
    if (i < n) g_fill[i] = g_rowptr[i];
}

__global__ void k_scatter(const int* __restrict__ src, const int* __restrict__ dst, int E) {
    int i = blockIdx.x * blockDim.x + threadIdx.x;
    if (i < E) {
        int pos = atomicAdd(&g_fill[dst[i]], 1);
        g_csr[pos] = src[i];
    }
}

// ---------------- mean aggregation: warp per destination node --------------
__global__ void k_agg(const float* __restrict__ h_in, int M) {
    const float* __restrict__ h = h_in ? h_in : g_h1;
    int node = (blockIdx.x * blockDim.x + threadIdx.x) >> 5;
    if (node >= M) return;
    int lane = threadIdx.x & 31;
    int s0 = g_rowptr[node], s1 = g_rowptr[node + 1];
    float4 acc = make_float4(0.f, 0.f, 0.f, 0.f);
    int i = s0;
    for (; i + 1 < s1; i += 2) {
        int a = g_csr[i], b = g_csr[i + 1];
        float4 v1 = *(const float4*)(h + (size_t)a * F + lane * 4);
        float4 v2 = *(const float4*)(h + (size_t)b * F + lane * 4);
        acc.x += v1.x + v2.x; acc.y += v1.y + v2.y;
        acc.z += v1.z + v2.z; acc.w += v1.w + v2.w;
    }
    if (i < s1) {
        int a = g_csr[i];
        float4 v1 = *(const float4*)(h + (size_t)a * F + lane * 4);
        acc.x += v1.x; acc.y += v1.y; acc.z += v1.z; acc.w += v1.w;
    }
    int deg = s1 - s0;
    float inv = 1.0f / (float)max(deg, 1);
    acc.x *= inv; acc.y *= inv; acc.z *= inv; acc.w *= inv;
    *(float4*)(g_mean + (size_t)node * F + lane * 4) = acc;
}

// ---------------- tf32 MMA helpers -----------------------------------------
__device__ __forceinline__ uint32_t cvt_tf32(float x) {
    uint32_t r;
    asm("cvt.rna.tf32.f32 %0, %1;" : "=r"(r) : "f"(x));
    return r;
}

__device__ __forceinline__ void mma_tf32(float* c, const uint32_t* a, const uint32_t* b) {
    asm volatile(
        "mma.sync.aligned.m16n8k8.row.col.f32.tf32.tf32.f32 "
        "{%0,%1,%2,%3}, {%4,%5,%6,%7}, {%8,%9}, {%0,%1,%2,%3};"
        : "+f"(c[0]), "+f"(c[1]), "+f"(c[2]), "+f"(c[3])
        : "r"(a[0]), "r"(a[1]), "r"(a[2]), "r"(a[3]), "r"(b[0]), "r"(b[1]));
}

// ---------------- fused dual-GEMM via tensor cores --------------------------
// out[M,128] = hs @ Ws + g_mean @ Wn + b   (+ optional leaky relu)
// CTA tile 128x128; 8 warps as 2(m) x 4(n); warp tile 64x32 (4 m16 x 4 n8).
#define APAD 40
#define BPAD 136
template <bool LEAKY>
__global__ void __launch_bounds__(256)
k_gemm_mma(const float* __restrict__ hs_in,
           const float* __restrict__ Ws, const float* __restrict__ Wn,
           const float* __restrict__ bias,
           float* __restrict__ out_in, int M) {
    const float* __restrict__ hs = hs_in ? hs_in : g_h1;
    float* __restrict__ out = out_in ? out_in : g_h1;

    __shared__ uint32_t As[128 * APAD];   // [m][k], 20 KB
    __shared__ uint32_t Bs[32 * BPAD];    // [k][n], 17 KB

    int tid = threadIdx.x;
    int wid = tid >> 5, lane = tid & 31;
    int warp_m = (wid & 1) * 64;
    int warp_n = (wid >> 1) * 32;
    int base = blockIdx.x * 128;
    int qr = lane >> 2, qc = lane & 3;

    float acc[4][4][4];
#pragma unroll
    for (int a = 0; a < 4; a++)
#pragma unroll
        for (int b = 0; b < 4; b++)
#pragma unroll
            for (int c = 0; c < 4; c++) acc[a][b][c] = 0.f;

#pragma unroll
    for (int p = 0; p < 2; p++) {
        const float* __restrict__ A = p ? g_mean : hs;
        const float* __restrict__ W = p ? Wn : Ws;
#pragma unroll
        for (int kc = 0; kc < F; kc += 32) {
            // load A chunk [128 x 32] -> As[m][k]
#pragma unroll
            for (int i = 0; i < 4; i++) {
                int idx = tid + i * 256;
                int r = idx >> 3, c4 = (idx & 7) << 2;
                float4 v = make_float4(0.f, 0.f, 0.f, 0.f);
                int gr = base + r;
                if (gr < M) v = *(const float4*)(A + (size_t)gr * F + kc + c4);
                uint32_t* d = &As[r * APAD + c4];
                d[0] = cvt_tf32(v.x); d[1] = cvt_tf32(v.y);
                d[2] = cvt_tf32(v.z); d[3] = cvt_tf32(v.w);
            }
            // load W chunk [32 x 128] -> Bs[k][n]
#pragma unroll
            for (int i = 0; i < 4; i++) {
                int idx = tid + i * 256;
                int r = idx >> 5, c4 = (idx & 31) << 2;
                float4 v = *(const float4*)(W + (size_t)(kc + r) * F + c4);
                uint32_t* d = &Bs[r * BPAD + c4];
                d[0] = cvt_tf32(v.x); d[1] = cvt_tf32(v.y);
                d[2] = cvt_tf32(v.z); d[3] = cvt_tf32(v.w);
            }
            __syncthreads();
#pragma unroll
            for (int k8 = 0; k8 < 32; k8 += 8) {
                uint32_t bfr[4][2];
#pragma unroll
                for (int nt = 0; nt < 4; nt++) {
                    int n = warp_n + nt * 8 + qr;
                    bfr[nt][0] = Bs[(k8 + qc) * BPAD + n];
                    bfr[nt][1] = Bs[(k8 + qc + 4) * BPAD + n];
                }
#pragma unroll
                for (int mt = 0; mt < 4; mt++) {
                    int m = warp_m + mt * 16;
                    uint32_t afr[4];
                    afr[0] = As[(m + qr) * APAD + k8 + qc];
                    afr[1] = As[(m + qr + 8) * APAD + k8 + qc];
                    afr[2] = As[(m + qr) * APAD + k8 + qc + 4];
                    afr[3] = As[(m + qr + 8) * APAD + k8 + qc + 4];
#pragma unroll
                    for (int nt = 0; nt < 4; nt++)
                        mma_tf32(acc[mt][nt], afr, bfr[nt]);
                }
            }
            __syncthreads();
        }
    }

    // epilogue: c0/c1 at (row=qr, col=2qc..2qc+1), c2/c3 at row=qr+8
#pragma unroll
    for (int nt = 0; nt < 4; nt++) {
        int col = warp_n + nt * 8 + 2 * qc;
        float b0 = bias[col], b1 = bias[col + 1];
#pragma unroll
        for (int mt = 0; mt < 4; mt++) {
#pragma unroll
            for (int h = 0; h < 2; h++) {
                int row = base + warp_m + mt * 16 + qr + h * 8;
                if (row < M) {
                    float v0 = acc[mt][nt][2 * h] + b0;
                    float v1 = acc[mt][nt][2 * h + 1] + b1;
                    if (LEAKY) {
                        v0 = v0 > 0.f ? v0 : 0.2f * v0;
                        v1 = v1 > 0.f ? v1 : 0.2f * v1;
                    }
                    float2 vv = make_float2(v0, v1);
                    *(float2*)(out + (size_t)row * F + col) = vv;
                }
            }
        }
    }
}

// ---------------- launch ----------------------------------------------------
extern "C" void kernel_launch(void* const* d_in, const int* in_sizes, int n_in,
                              void* d_out, int out_size) {
    const float* emb = (const float*)d_in[0];
    const float* W1s = (const float*)d_in[1];
    const float* W1n = (const float*)d_in[2];
    const float* b1  = (const float*)d_in[3];
    const float* W2s = (const float*)d_in[4];
    const float* W2n = (const float*)d_in[5];
    const float* b2  = (const float*)d_in[6];
    const int*   edg = (const int*)d_in[7];

    int E = in_sizes[7] / 2;
    int M = in_sizes[0] / F;
    const int* src = edg;
    const int* dst = edg + E;
    float* out = (float*)d_out;

    // CSR by destination (once; shared by both layers)
    k_zero<<<(M + 1 + 255) / 256, 256>>>(M + 1);
    k_hist<<<(E + 255) / 256, 256>>>(dst, E);
    k_scan<<<1, 1024>>>(M + 1);
    k_fill<<<(M + 255) / 256, 256>>>(M);
    k_scatter<<<(E + 255) / 256, 256>>>(src, dst, E);

    int aggBlocks = (M * 32 + 255) / 256;
    int gemmBlocks = (M + 127) / 128;

    // layer 1
    k_agg<<<aggBlocks, 256>>>(emb, M);
    k_gemm_mma<true><<<gemmBlocks, 256>>>(emb, W1s, W1n, b1, nullptr, M);

    // layer 2
    k_agg<<<aggBlocks, 256>>>(nullptr, M);
    k_gemm_mma<false><<<gemmBlocks, 256>>>(nullptr, W2s, W2n, b2, out, M);
}

// round 3
// speedup vs baseline: 1.0973x; 1.0911x over previous
#include <cuda_runtime.h>
#include <cstdint>

#define NN 100000
#define NE 1600000
#define F  128

// ---------------- scratch (device globals: no allocation allowed) ----------
__device__ __align__(16) float g_mean[(size_t)NN * F];   // 51.2 MB
__device__ __align__(16) float g_h1[(size_t)NN * F];     // 51.2 MB
__device__ int g_rowptr[NN + 1];
__device__ int g_fill[NN];
__device__ int g_csr[NE];
__device__ int g_tilesum[64];
__device__ int g_tileoff[64];

// ---------------- CSR build ------------------------------------------------
__global__ void k_zero(int n) {
    int i = blockIdx.x * blockDim.x + threadIdx.x;
    if (i < n) g_rowptr[i] = 0;
}

__global__ void k_hist(const int* __restrict__ dst, int E) {
    int i = blockIdx.x * blockDim.x + threadIdx.x;
    if (i < E) atomicAdd(&g_rowptr[dst[i] + 1], 1);
}

// ---- parallel scan: phase 1 — per-block (4096 elems) inclusive scan --------
#define SCAN_TILE 4096
__global__ void __launch_bounds__(1024) k_scan1(int n) {
    __shared__ int ws[32];
    int t = threadIdx.x;
    int lane = t & 31, wid = t >> 5;
    int base = blockIdx.x * SCAN_TILE + t * 4;
    int v[4];
#pragma unroll
    for (int j = 0; j < 4; j++) v[j] = (base + j < n) ? g_rowptr[base + j] : 0;
    int s = v[0] + v[1] + v[2] + v[3];
    int sv = s;
#pragma unroll
    for (int o = 1; o < 32; o <<= 1) {
        int tmp = __shfl_up_sync(0xffffffffu, sv, o);
        if (lane >= o) sv += tmp;
    }
    if (lane == 31) ws[wid] = sv;
    __syncthreads();
    if (wid == 0) {
        int w = (lane < 32) ? ws[lane] : 0;
#pragma unroll
        for (int o = 1; o < 32; o <<= 1) {
            int tmp = __shfl_up_sync(0xffffffffu, w, o);
            if (lane >= o) w += tmp;
        }
        ws[lane] = w;
    }
    __syncthreads();
    int excl = sv - s + (wid > 0 ? ws[wid - 1] : 0);
    int run = excl;
#pragma unroll
    for (int j = 0; j < 4; j++) {
        run += v[j];
        if (base + j < n) g_rowptr[base + j] = run;
    }
    if (t == 1023) g_tilesum[blockIdx.x] = ws[31];
}

// ---- phase 2 — single warp scans tile sums (exclusive) ---------------------
__global__ void k_scan2(int nblocks) {
    int lane = threadIdx.x;
    int v = (lane < nblocks) ? g_tilesum[lane] : 0;
    int sv = v;
#pragma unroll
    for (int o = 1; o < 32; o <<= 1) {
        int t = __shfl_up_sync(0xffffffffu, sv, o);
        if (lane >= o) sv += t;
    }
    if (lane < nblocks) g_tileoff[lane] = sv - v;   // exclusive
}

// ---- phase 3 — add tile offsets; also produce g_fill ------------------------
__global__ void __launch_bounds__(1024) k_scan3(int n) {
    int off = g_tileoff[blockIdx.x];
    int base = blockIdx.x * SCAN_TILE + threadIdx.x * 4;
#pragma unroll
    for (int j = 0; j < 4; j++) {
        int i = base + j;
        if (i < n) {
            int val = g_rowptr[i] + off;
            g_rowptr[i] = val;
            if (i < n - 1) g_fill[i] = val;
        }
    }
}

__global__ void k_scatter(const int* __restrict__ src, const int* __restrict__ dst, int E) {
    int i = blockIdx.x * blockDim.x + threadIdx.x;
    if (i < E) {
        int pos = atomicAdd(&g_fill[dst[i]], 1);
        g_csr[pos] = src[i];
    }
}

// ---------------- mean aggregation: warp per node, MLP-8 gathers ------------
__global__ void k_agg(const float* __restrict__ h_in, int M) {
    const float* __restrict__ h = h_in ? h_in : g_h1;
    int node = (blockIdx.x * blockDim.x + threadIdx.x) >> 5;
    if (node >= M) return;
    int lane = threadIdx.x & 31;
    int s0 = g_rowptr[node], s1 = g_rowptr[node + 1];
    int deg = s1 - s0;
    float4 acc = make_float4(0.f, 0.f, 0.f, 0.f);
    int c = s0;
    while (c < s1) {
        int cnt = min(32, s1 - c);
        int idx = 0;
        if (lane < cnt) idx = g_csr[c + lane];       // coalesced index load
        int j = 0;
        for (; j + 8 <= cnt; j += 8) {
            float4 v[8];
#pragma unroll
            for (int u = 0; u < 8; u++) {
                int a = __shfl_sync(0xffffffffu, idx, j + u);
                v[u] = *(const float4*)(h + (size_t)a * F + lane * 4);
            }
#pragma unroll
            for (int u = 0; u < 8; u++) {
                acc.x += v[u].x; acc.y += v[u].y;
                acc.z += v[u].z; acc.w += v[u].w;
            }
        }
        if (j < cnt) {
            float4 v[8];
            int rem = cnt - j;
#pragma unroll
            for (int u = 0; u < 8; u++) {
                if (u < rem) {
                    int a = __shfl_sync(0xffffffffu, idx, j + u);
                    v[u] = *(const float4*)(h + (size_t)a * F + lane * 4);
                } else {
                    v[u] = make_float4(0.f, 0.f, 0.f, 0.f);
                }
            }
#pragma unroll
            for (int u = 0; u < 8; u++) {
                acc.x += v[u].x; acc.y += v[u].y;
                acc.z += v[u].z; acc.w += v[u].w;
            }
        }
        c += cnt;
    }
    float inv = 1.0f / (float)max(deg, 1);
    acc.x *= inv; acc.y *= inv; acc.z *= inv; acc.w *= inv;
    *(float4*)(g_mean + (size_t)node * F + lane * 4) = acc;
}

// ---------------- tf32 MMA helpers -----------------------------------------
__device__ __forceinline__ uint32_t cvt_tf32(float x) {
    uint32_t r;
    asm("cvt.rna.tf32.f32 %0, %1;" : "=r"(r) : "f"(x));
    return r;
}

__device__ __forceinline__ void mma_tf32(float* c, const uint32_t* a, const uint32_t* b) {
    asm volatile(
        "mma.sync.aligned.m16n8k8.row.col.f32.tf32.tf32.f32 "
        "{%0,%1,%2,%3}, {%4,%5,%6,%7}, {%8,%9}, {%0,%1,%2,%3};"
        : "+f"(c[0]), "+f"(c[1]), "+f"(c[2]), "+f"(c[3])
        : "r"(a[0]), "r"(a[1]), "r"(a[2]), "r"(a[3]), "r"(b[0]), "r"(b[1]));
}

// ---------------- fused dual-GEMM via tensor cores --------------------------
#define APAD 40
#define BPAD 136
template <bool LEAKY>
__global__ void __launch_bounds__(256)
k_gemm_mma(const float* __restrict__ hs_in,
           const float* __restrict__ Ws, const float* __restrict__ Wn,
           const float* __restrict__ bias,
           float* __restrict__ out_in, int M) {
    const float* __restrict__ hs = hs_in ? hs_in : g_h1;
    float* __restrict__ out = out_in ? out_in : g_h1;

    __shared__ uint32_t As[128 * APAD];
    __shared__ uint32_t Bs[32 * BPAD];

    int tid = threadIdx.x;
    int wid = tid >> 5, lane = tid & 31;
    int warp_m = (wid & 1) * 64;
    int warp_n = (wid >> 1) * 32;
    int base = blockIdx.x * 128;
    int qr = lane >> 2, qc = lane & 3;

    float acc[4][4][4];
#pragma unroll
    for (int a = 0; a < 4; a++)
#pragma unroll
        for (int b = 0; b < 4; b++)
#pragma unroll
            for (int c = 0; c < 4; c++) acc[a][b][c] = 0.f;

#pragma unroll
    for (int p = 0; p < 2; p++) {
        const float* __restrict__ A = p ? g_mean : hs;
        const float* __restrict__ W = p ? Wn : Ws;
#pragma unroll
        for (int kc = 0; kc < F; kc += 32) {
#pragma unroll
            for (int i = 0; i < 4; i++) {
                int idx = tid + i * 256;
                int r = idx >> 3, c4 = (idx & 7) << 2;
                float4 v = make_float4(0.f, 0.f, 0.f, 0.f);
                int gr = base + r;
                if (gr < M) v = *(const float4*)(A + (size_t)gr * F + kc + c4);
                uint32_t* d = &As[r * APAD + c4];
                d[0] = cvt_tf32(v.x); d[1] = cvt_tf32(v.y);
                d[2] = cvt_tf32(v.z); d[3] = cvt_tf32(v.w);
            }
#pragma unroll
            for (int i = 0; i < 4; i++) {
                int idx = tid + i * 256;
                int r = idx >> 5, c4 = (idx & 31) << 2;
                float4 v = *(const float4*)(W + (size_t)(kc + r) * F + c4);
                uint32_t* d = &Bs[r * BPAD + c4];
                d[0] = cvt_tf32(v.x); d[1] = cvt_tf32(v.y);
                d[2] = cvt_tf32(v.z); d[3] = cvt_tf32(v.w);
            }
            __syncthreads();
#pragma unroll
            for (int k8 = 0; k8 < 32; k8 += 8) {
                uint32_t bfr[4][2];
#pragma unroll
                for (int nt = 0; nt < 4; nt++) {
                    int n = warp_n + nt * 8 + qr;
                    bfr[nt][0] = Bs[(k8 + qc) * BPAD + n];
                    bfr[nt][1] = Bs[(k8 + qc + 4) * BPAD + n];
                }
#pragma unroll
                for (int mt = 0; mt < 4; mt++) {
                    int m = warp_m + mt * 16;
                    uint32_t afr[4];
                    afr[0] = As[(m + qr) * APAD + k8 + qc];
                    afr[1] = As[(m + qr + 8) * APAD + k8 + qc];
                    afr[2] = As[(m + qr) * APAD + k8 + qc + 4];
                    afr[3] = As[(m + qr + 8) * APAD + k8 + qc + 4];
#pragma unroll
                    for (int nt = 0; nt < 4; nt++)
                        mma_tf32(acc[mt][nt], afr, bfr[nt]);
                }
            }
            __syncthreads();
        }
    }

#pragma unroll
    for (int nt = 0; nt < 4; nt++) {
        int col = warp_n + nt * 8 + 2 * qc;
        float b0 = bias[col], b1 = bias[col + 1];
#pragma unroll
        for (int mt = 0; mt < 4; mt++) {
#pragma unroll
            for (int h = 0; h < 2; h++) {
                int row = base + warp_m + mt * 16 + qr + h * 8;
                if (row < M) {
                    float v0 = acc[mt][nt][2 * h] + b0;
                    float v1 = acc[mt][nt][2 * h + 1] + b1;
                    if (LEAKY) {
                        v0 = v0 > 0.f ? v0 : 0.2f * v0;
                        v1 = v1 > 0.f ? v1 : 0.2f * v1;
                    }
                    float2 vv = make_float2(v0, v1);
                    *(float2*)(out + (size_t)row * F + col) = vv;
                }
            }
        }
    }
}

// ---------------- launch ----------------------------------------------------
extern "C" void kernel_launch(void* const* d_in, const int* in_sizes, int n_in,
                              void* d_out, int out_size) {
    const float* emb = (const float*)d_in[0];
    const float* W1s = (const float*)d_in[1];
    const float* W1n = (const float*)d_in[2];
    const float* b1  = (const float*)d_in[3];
    const float* W2s = (const float*)d_in[4];
    const float* W2n = (const float*)d_in[5];
    const float* b2  = (const float*)d_in[6];
    const int*   edg = (const int*)d_in[7];

    int E = in_sizes[7] / 2;
    int M = in_sizes[0] / F;
    const int* src = edg;
    const int* dst = edg + E;
    float* out = (float*)d_out;

    int n = M + 1;
    int scanBlocks = (n + SCAN_TILE - 1) / SCAN_TILE;   // 25 for 100001

    k_zero<<<(n + 255) / 256, 256>>>(n);
    k_hist<<<(E + 255) / 256, 256>>>(dst, E);
    k_scan1<<<scanBlocks, 1024>>>(n);
    k_scan2<<<1, 32>>>(scanBlocks);
    k_scan3<<<scanBlocks, 1024>>>(n);
    k_scatter<<<(E + 255) / 256, 256>>>(src, dst, E);

    int aggBlocks = (M * 32 + 255) / 256;
    int gemmBlocks = (M + 127) / 128;

    // layer 1
    k_agg<<<aggBlocks, 256>>>(emb, M);
    k_gemm_mma<true><<<gemmBlocks, 256>>>(emb, W1s, W1n, b1, nullptr, M);

    // layer 2
    k_agg<<<aggBlocks, 256>>>(nullptr, M);
    k_gemm_mma<false><<<gemmBlocks, 256>>>(nullptr, W2s, W2n, b2, out, M);
}

// round 4
// speedup vs baseline: 1.6982x; 1.5475x over previous
#include <cuda_runtime.h>
#include <cstdint>

#define NN 100000
#define NE 1600000
#define F  128

// ---------------- scratch (device globals: no allocation allowed) ----------
__device__ __align__(16) float g_mean[(size_t)NN * F];   // 51.2 MB
__device__ __align__(16) float g_h1[(size_t)NN * F];     // 51.2 MB
__device__ int g_rowptr[NN + 1];
__device__ int g_fill[NN];
__device__ int g_csr[NE];
__device__ int g_tilesum[64];

// ---------------- CSR build ------------------------------------------------
__global__ void k_zero(int n) {
    int i = blockIdx.x * blockDim.x + threadIdx.x;
    if (i < n) g_rowptr[i] = 0;
}

__global__ void k_hist(const int* __restrict__ dst, int E) {
    int i = blockIdx.x * blockDim.x + threadIdx.x;
    if (i < E) atomicAdd(&g_rowptr[dst[i] + 1], 1);
}

// ---- parallel scan: phase 1 — per-block (4096 elems) inclusive scan --------
#define SCAN_TILE 4096
__global__ void __launch_bounds__(1024) k_scan1(int n) {
    __shared__ int ws[32];
    int t = threadIdx.x;
    int lane = t & 31, wid = t >> 5;
    int base = blockIdx.x * SCAN_TILE + t * 4;
    int v[4];
#pragma unroll
    for (int j = 0; j < 4; j++) v[j] = (base + j < n) ? g_rowptr[base + j] : 0;
    int s = v[0] + v[1] + v[2] + v[3];
    int sv = s;
#pragma unroll
    for (int o = 1; o < 32; o <<= 1) {
        int tmp = __shfl_up_sync(0xffffffffu, sv, o);
        if (lane >= o) sv += tmp;
    }
    if (lane == 31) ws[wid] = sv;
    __syncthreads();
    if (wid == 0) {
        int w = ws[lane];
#pragma unroll
        for (int o = 1; o < 32; o <<= 1) {
            int tmp = __shfl_up_sync(0xffffffffu, w, o);
            if (lane >= o) w += tmp;
        }
        ws[lane] = w;
    }
    __syncthreads();
    int excl = sv - s + (wid > 0 ? ws[wid - 1] : 0);
    int run = excl;
#pragma unroll
    for (int j = 0; j < 4; j++) {
        run += v[j];
        if (base + j < n) g_rowptr[base + j] = run;
    }
    if (t == 1023) g_tilesum[blockIdx.x] = ws[31];
}

// ---- phase 2+3 fused — per-block: warp-scan tile sums, add offset, emit fill
__global__ void __launch_bounds__(1024) k_scan3(int n, int nblocks) {
    __shared__ int s_off;
    if (threadIdx.x < 32) {
        int lane = threadIdx.x;
        int v = (lane < nblocks) ? g_tilesum[lane] : 0;
        int sv = v;
#pragma unroll
        for (int o = 1; o < 32; o <<= 1) {
            int t = __shfl_up_sync(0xffffffffu, sv, o);
            if (lane >= o) sv += t;
        }
        if (lane == blockIdx.x) s_off = sv - v;   // exclusive prefix for this tile
    }
    __syncthreads();
    int off = s_off;
    int base = blockIdx.x * SCAN_TILE + threadIdx.x * 4;
#pragma unroll
    for (int j = 0; j < 4; j++) {
        int i = base + j;
        if (i < n) {
            int val = g_rowptr[i] + off;
            g_rowptr[i] = val;
            if (i < n - 1) g_fill[i] = val;
        }
    }
}

__global__ void k_scatter(const int* __restrict__ src, const int* __restrict__ dst, int E) {
    int i = blockIdx.x * blockDim.x + threadIdx.x;
    if (i < E) {
        int pos = atomicAdd(&g_fill[dst[i]], 1);
        g_csr[pos] = src[i];
    }
}

// ---------------- mean aggregation: warp per node, MLP-8 gathers ------------
__global__ void k_agg(const float* __restrict__ h_in, int M) {
    const float* __restrict__ h = h_in ? h_in : g_h1;
    int node = (blockIdx.x * blockDim.x + threadIdx.x) >> 5;
    if (node >= M) return;
    int lane = threadIdx.x & 31;
    int s0 = g_rowptr[node], s1 = g_rowptr[node + 1];
    int deg = s1 - s0;
    float4 acc = make_float4(0.f, 0.f, 0.f, 0.f);
    int c = s0;
    while (c < s1) {
        int cnt = min(32, s1 - c);
        int idx = 0;
        if (lane < cnt) idx = g_csr[c + lane];
        int j = 0;
        for (; j + 8 <= cnt; j += 8) {
            float4 v[8];
#pragma unroll
            for (int u = 0; u < 8; u++) {
                int a = __shfl_sync(0xffffffffu, idx, j + u);
                v[u] = *(const float4*)(h + (size_t)a * F + lane * 4);
            }
#pragma unroll
            for (int u = 0; u < 8; u++) {
                acc.x += v[u].x; acc.y += v[u].y;
                acc.z += v[u].z; acc.w += v[u].w;
            }
        }
        if (j < cnt) {
            float4 v[8];
            int rem = cnt - j;
#pragma unroll
            for (int u = 0; u < 8; u++) {
                if (u < rem) {
                    int a = __shfl_sync(0xffffffffu, idx, j + u);
                    v[u] = *(const float4*)(h + (size_t)a * F + lane * 4);
                } else {
                    v[u] = make_float4(0.f, 0.f, 0.f, 0.f);
                }
            }
#pragma unroll
            for (int u = 0; u < 8; u++) {
                acc.x += v[u].x; acc.y += v[u].y;
                acc.z += v[u].z; acc.w += v[u].w;
            }
        }
        c += cnt;
    }
    float inv = 1.0f / (float)max(deg, 1);
    acc.x *= inv; acc.y *= inv; acc.z *= inv; acc.w *= inv;
    *(float4*)(g_mean + (size_t)node * F + lane * 4) = acc;
}

// ---------------- tf32 MMA / cp.async helpers --------------------------------
__device__ __forceinline__ uint32_t cvt_tf32(float x) {
    uint32_t r;
    asm("cvt.rna.tf32.f32 %0, %1;" : "=r"(r) : "f"(x));
    return r;
}

__device__ __forceinline__ void mma_tf32(float* c, const uint32_t* a, const uint32_t* b) {
    asm volatile(
        "mma.sync.aligned.m16n8k8.row.col.f32.tf32.tf32.f32 "
        "{%0,%1,%2,%3}, {%4,%5,%6,%7}, {%8,%9}, {%0,%1,%2,%3};"
        : "+f"(c[0]), "+f"(c[1]), "+f"(c[2]), "+f"(c[3])
        : "r"(a[0]), "r"(a[1]), "r"(a[2]), "r"(a[3]), "r"(b[0]), "r"(b[1]));
}

__device__ __forceinline__ void cp16(uint32_t dst, const void* src, int sz) {
    asm volatile("cp.async.cg.shared.global [%0], [%1], 16, %2;\n"
                 :: "r"(dst), "l"(src), "r"(sz));
}
__device__ __forceinline__ void cp_commit() {
    asm volatile("cp.async.commit_group;\n" ::: "memory");
}
template <int N>
__device__ __forceinline__ void cp_wait() {
    asm volatile("cp.async.wait_group %0;\n" :: "n"(N) : "memory");
}

// ---------------- fused dual-GEMM, cp.async double-buffered ------------------
// out[M,128] = hs @ Ws + g_mean @ Wn + b  (+ leaky). CTA 128x128, BK=16,
// 8 warps (2m x 4n), warp tile 64x32. fp32 in smem; cvt->tf32 at frag load.
#define AST 20    // A smem row stride (floats): (20*qr+qc)%32 distinct
#define BST 136   // B smem row stride (floats): (8*qc+qr)%32 distinct
template <bool LEAKY>
__global__ void __launch_bounds__(256)
k_gemm_mma(const float* __restrict__ hs_in,
           const float* __restrict__ Ws, const float* __restrict__ Wn,
           const float* __restrict__ bias,
           float* __restrict__ out_in, int M) {
    const float* __restrict__ hs = hs_in ? hs_in : g_h1;
    float* __restrict__ out = out_in ? out_in : g_h1;

    __shared__ float As[2][128 * AST];   // 20 KB
    __shared__ float Bs[2][16 * BST];    // 17 KB

    int tid = threadIdx.x;
    int wid = tid >> 5, lane = tid & 31;
    int warp_m = (wid & 1) * 64;
    int warp_n = (wid >> 1) * 32;
    int base = blockIdx.x * 128;
    int qr = lane >> 2, qc = lane & 3;

    uint32_t as_base = (uint32_t)__cvta_generic_to_shared(&As[0][0]);
    uint32_t bs_base = (uint32_t)__cvta_generic_to_shared(&Bs[0][0]);

    // staging mapping (computed once)
    int a_r0 = tid >> 2, a_s0 = (tid & 3) * 4;          // idx j=0
    int a_r1 = (tid + 256) >> 2, a_s1 = a_s0;           // idx j=1 (same seg)
    int b_r0 = tid >> 5, b_s0 = (tid & 31) * 4;
    int b_r1 = b_r0 + 8, b_s1 = b_s0;

    float acc[4][4][4];
#pragma unroll
    for (int a = 0; a < 4; a++)
#pragma unroll
        for (int b = 0; b < 4; b++)
#pragma unroll
            for (int c = 0; c < 4; c++) acc[a][b][c] = 0.f;

    // chunk c in [0,16): pass p=c>>3 selects (A,W); kc=(c&7)*16
#define LOAD_CHUNK(c, buf)                                                      \
    {                                                                           \
        int p_ = (c) >> 3, kc_ = ((c) & 7) * 16;                                \
        const float* A_ = p_ ? g_mean : hs;                                     \
        const float* W_ = p_ ? Wn : Ws;                                         \
        uint32_t ab = as_base + (uint32_t)(buf) * 128 * AST * 4;                \
        uint32_t bb = bs_base + (uint32_t)(buf) * 16 * BST * 4;                 \
        cp16(ab + (a_r0 * AST + a_s0) * 4,                                      \
             A_ + (size_t)(base + a_r0) * F + kc_ + a_s0,                       \
             (base + a_r0 < M) ? 16 : 0);                                       \
        cp16(ab + (a_r1 * AST + a_s1) * 4,                                      \
             A_ + (size_t)(base + a_r1) * F + kc_ + a_s1,                       \
             (base + a_r1 < M) ? 16 : 0);                                       \
        cp16(bb + (b_r0 * BST + b_s0) * 4, W_ + (size_t)(kc_ + b_r0) * F + b_s0, 16); \
        cp16(bb + (b_r1 * BST + b_s1) * 4, W_ + (size_t)(kc_ + b_r1) * F + b_s1, 16); \
    }

    LOAD_CHUNK(0, 0);
    cp_commit();

    for (int c = 0; c < 16; ++c) {
        cp_wait<0>();
        __syncthreads();
        int buf = c & 1;
        if (c + 1 < 16) {
            LOAD_CHUNK(c + 1, buf ^ 1);
            cp_commit();
        }
        const float* as = As[buf];
        const float* bs = Bs[buf];
#pragma unroll
        for (int k8 = 0; k8 < 16; k8 += 8) {
            uint32_t bfr[4][2];
#pragma unroll
            for (int nt = 0; nt < 4; nt++) {
                int n = warp_n + nt * 8 + qr;
                bfr[nt][0] = cvt_tf32(bs[(k8 + qc) * BST + n]);
                bfr[nt][1] = cvt_tf32(bs[(k8 + qc + 4) * BST + n]);
            }
#pragma unroll
            for (int mt = 0; mt < 4; mt++) {
                int m = warp_m + mt * 16;
                uint32_t afr[4];
                afr[0] = cvt_tf32(as[(m + qr) * AST + k8 + qc]);
                afr[1] = cvt_tf32(as[(m + qr + 8) * AST + k8 + qc]);
                afr[2] = cvt_tf32(as[(m + qr) * AST + k8 + qc + 4]);
                afr[3] = cvt_tf32(as[(m + qr + 8) * AST + k8 + qc + 4]);
#pragma unroll
                for (int nt = 0; nt < 4; nt++)
                    mma_tf32(acc[mt][nt], afr, bfr[nt]);
            }
        }
        __syncthreads();
    }

    // epilogue
#pragma unroll
    for (int nt = 0; nt < 4; nt++) {
        int col = warp_n + nt * 8 + 2 * qc;
        float b0 = bias[col], b1 = bias[col + 1];
#pragma unroll
        for (int mt = 0; mt < 4; mt++) {
#pragma unroll
            for (int h = 0; h < 2; h++) {
                int row = base + warp_m + mt * 16 + qr + h * 8;
                if (row < M) {
                    float v0 = acc[mt][nt][2 * h] + b0;
                    float v1 = acc[mt][nt][2 * h + 1] + b1;
                    if (LEAKY) {
                        v0 = v0 > 0.f ? v0 : 0.2f * v0;
                        v1 = v1 > 0.f ? v1 : 0.2f * v1;
                    }
                    float2 vv = make_float2(v0, v1);
                    *(float2*)(out + (size_t)row * F + col) = vv;
                }
            }
        }
    }
#undef LOAD_CHUNK
}

// ---------------- launch ----------------------------------------------------
extern "C" void kernel_launch(void* const* d_in, const int* in_sizes, int n_in,
                              void* d_out, int out_size) {
    const float* emb = (const float*)d_in[0];
    const float* W1s = (const float*)d_in[1];
    const float* W1n = (const float*)d_in[2];
    const float* b1  = (const float*)d_in[3];
    const float* W2s = (const float*)d_in[4];
    const float* W2n = (const float*)d_in[5];
    const float* b2  = (const float*)d_in[6];
    const int*   edg = (const int*)d_in[7];

    int E = in_sizes[7] / 2;
    int M = in_sizes[0] / F;
    const int* src = edg;
    const int* dst = edg + E;
    float* out = (float*)d_out;

    int n = M + 1;
    int scanBlocks = (n + SCAN_TILE - 1) / SCAN_TILE;

    k_zero<<<(n + 255) / 256, 256>>>(n);
    k_hist<<<(E + 255) / 256, 256>>>(dst, E);
    k_scan1<<<scanBlocks, 1024>>>(n);
    k_scan3<<<scanBlocks, 1024>>>(n, scanBlocks);
    k_scatter<<<(E + 255) / 256, 256>>>(src, dst, E);

    int aggBlocks = (M * 32 + 255) / 256;
    int gemmBlocks = (M + 127) / 128;

    // layer 1
    k_agg<<<aggBlocks, 256>>>(emb, M);
    k_gemm_mma<true><<<gemmBlocks, 256>>>(emb, W1s, W1n, b1, nullptr, M);

    // layer 2
    k_agg<<<aggBlocks, 256>>>(nullptr, M);
    k_gemm_mma<false><<<gemmBlocks, 256>>>(nullptr, W2s, W2n, b2, out, M);
}

// round 5
// speedup vs baseline: 1.8329x; 1.0793x over previous
#include <cuda_runtime.h>
#include <cuda_fp16.h>
#include <cstdint>

#define NN 100000
#define NE 1600000
#define F  128

// ---------------- scratch (device globals: no allocation allowed) ----------
__device__ __align__(16) float  g_mean[(size_t)NN * F];   // 51.2 MB
__device__ __align__(16) float  g_h1[(size_t)NN * F];     // 51.2 MB
__device__ __align__(16) __half g_hhalf[(size_t)NN * F];  // 25.6 MB (gather mirror)
__device__ int g_rowptr[NN + 1];
__device__ int g_fill[NN];
__device__ int g_csr[NE];
__device__ int g_tilesum[64];

// ---------------- fp16 mirror of emb ----------------------------------------
__global__ void k_cvt(const float* __restrict__ src, int n4) {
    int i = blockIdx.x * blockDim.x + threadIdx.x;
    if (i < n4) {
        float4 v = *(const float4*)(src + (size_t)i * 4);
        __half2 h0 = __floats2half2_rn(v.x, v.y);
        __half2 h1 = __floats2half2_rn(v.z, v.w);
        uint2 u;
        u.x = *(uint32_t*)&h0; u.y = *(uint32_t*)&h1;
        *(uint2*)(g_hhalf + (size_t)i * 4) = u;
    }
}

// ---------------- CSR build ------------------------------------------------
__global__ void k_zero(int n) {
    int i = blockIdx.x * blockDim.x + threadIdx.x;
    if (i < n) g_rowptr[i] = 0;
}

__global__ void k_hist(const int* __restrict__ dst, int E) {
    int i = blockIdx.x * blockDim.x + threadIdx.x;
    if (i < E) atomicAdd(&g_rowptr[dst[i] + 1], 1);
}

#define SCAN_TILE 4096
__global__ void __launch_bounds__(1024) k_scan1(int n) {
    __shared__ int ws[32];
    int t = threadIdx.x;
    int lane = t & 31, wid = t >> 5;
    int base = blockIdx.x * SCAN_TILE + t * 4;
    int v[4];
#pragma unroll
    for (int j = 0; j < 4; j++) v[j] = (base + j < n) ? g_rowptr[base + j] : 0;
    int s = v[0] + v[1] + v[2] + v[3];
    int sv = s;
#pragma unroll
    for (int o = 1; o < 32; o <<= 1) {
        int tmp = __shfl_up_sync(0xffffffffu, sv, o);
        if (lane >= o) sv += tmp;
    }
    if (lane == 31) ws[wid] = sv;
    __syncthreads();
    if (wid == 0) {
        int w = ws[lane];
#pragma unroll
        for (int o = 1; o < 32; o <<= 1) {
            int tmp = __shfl_up_sync(0xffffffffu, w, o);
            if (lane >= o) w += tmp;
        }
        ws[lane] = w;
    }
    __syncthreads();
    int excl = sv - s + (wid > 0 ? ws[wid - 1] : 0);
    int run = excl;
#pragma unroll
    for (int j = 0; j < 4; j++) {
        run += v[j];
        if (base + j < n) g_rowptr[base + j] = run;
    }
    if (t == 1023) g_tilesum[blockIdx.x] = ws[31];
}

__global__ void __launch_bounds__(1024) k_scan3(int n, int nblocks) {
    __shared__ int s_off;
    if (threadIdx.x < 32) {
        int lane = threadIdx.x;
        int v = (lane < nblocks) ? g_tilesum[lane] : 0;
        int sv = v;
#pragma unroll
        for (int o = 1; o < 32; o <<= 1) {
            int t = __shfl_up_sync(0xffffffffu, sv, o);
            if (lane >= o) sv += t;
        }
        if (lane == blockIdx.x) s_off = sv - v;
    }
    __syncthreads();
    int off = s_off;
    int base = blockIdx.x * SCAN_TILE + threadIdx.x * 4;
#pragma unroll
    for (int j = 0; j < 4; j++) {
        int i = base + j;
        if (i < n) {
            int val = g_rowptr[i] + off;
            g_rowptr[i] = val;
            if (i < n - 1) g_fill[i] = val;
        }
    }
}

__global__ void k_scatter(const int* __restrict__ src, const int* __restrict__ dst, int E) {
    int i = blockIdx.x * blockDim.x + threadIdx.x;
    if (i < E) {
        int pos = atomicAdd(&g_fill[dst[i]], 1);
        g_csr[pos] = src[i];
    }
}

// ---------------- mean aggregation: warp per node, fp16 gather --------------
__device__ __forceinline__ void acc_row(float4& acc, int a, int lane) {
    uint2 u = *(const uint2*)(g_hhalf + (size_t)a * F + lane * 4);
    __half2 h0 = *(__half2*)&u.x, h1 = *(__half2*)&u.y;
    float2 f0 = __half22float2(h0), f1 = __half22float2(h1);
    acc.x += f0.x; acc.y += f0.y; acc.z += f1.x; acc.w += f1.y;
}

__global__ void k_agg(int M) {
    int node = (blockIdx.x * blockDim.x + threadIdx.x) >> 5;
    if (node >= M) return;
    int lane = threadIdx.x & 31;
    int s0 = g_rowptr[node], s1 = g_rowptr[node + 1];
    int deg = s1 - s0;
    float4 acc = make_float4(0.f, 0.f, 0.f, 0.f);
    int c = s0;
    while (c < s1) {
        int cnt = min(32, s1 - c);
        int idx = 0;
        if (lane < cnt) idx = g_csr[c + lane];
        int j = 0;
        for (; j + 8 <= cnt; j += 8) {
            uint2 u[8];
#pragma unroll
            for (int v = 0; v < 8; v++) {
                int a = __shfl_sync(0xffffffffu, idx, j + v);
                u[v] = *(const uint2*)(g_hhalf + (size_t)a * F + lane * 4);
            }
#pragma unroll
            for (int v = 0; v < 8; v++) {
                __half2 h0 = *(__half2*)&u[v].x, h1 = *(__half2*)&u[v].y;
                float2 f0 = __half22float2(h0), f1 = __half22float2(h1);
                acc.x += f0.x; acc.y += f0.y; acc.z += f1.x; acc.w += f1.y;
            }
        }
        for (; j < cnt; j++) {
            int a = __shfl_sync(0xffffffffu, idx, j);
            acc_row(acc, a, lane);
        }
        c += cnt;
    }
    float inv = 1.0f / (float)max(deg, 1);
    acc.x *= inv; acc.y *= inv; acc.z *= inv; acc.w *= inv;
    *(float4*)(g_mean + (size_t)node * F + lane * 4) = acc;
}

// ---------------- tf32 MMA / cp.async helpers --------------------------------
__device__ __forceinline__ uint32_t cvt_tf32(float x) {
    uint32_t r;
    asm("cvt.rna.tf32.f32 %0, %1;" : "=r"(r) : "f"(x));
    return r;
}

__device__ __forceinline__ void mma_tf32(float* c, const uint32_t* a, const uint32_t* b) {
    asm volatile(
        "mma.sync.aligned.m16n8k8.row.col.f32.tf32.tf32.f32 "
        "{%0,%1,%2,%3}, {%4,%5,%6,%7}, {%8,%9}, {%0,%1,%2,%3};"
        : "+f"(c[0]), "+f"(c[1]), "+f"(c[2]), "+f"(c[3])
        : "r"(a[0]), "r"(a[1]), "r"(a[2]), "r"(a[3]), "r"(b[0]), "r"(b[1]));
}

__device__ __forceinline__ void cp16(uint32_t dst, const void* src, int sz) {
    asm volatile("cp.async.cg.shared.global [%0], [%1], 16, %2;\n"
                 :: "r"(dst), "l"(src), "r"(sz));
}
__device__ __forceinline__ void cp_commit() {
    asm volatile("cp.async.commit_group;\n" ::: "memory");
}
template <int N>
__device__ __forceinline__ void cp_wait() {
    asm volatile("cp.async.wait_group %0;\n" :: "n"(N) : "memory");
}

// ---------------- fused dual-GEMM, cp.async double-buffered ------------------
#define AST 20
#define BST 136
template <bool LEAKY>   // LEAKY also means "layer 1": dual-write fp32 + fp16
__global__ void __launch_bounds__(256)
k_gemm_mma(const float* __restrict__ hs_in,
           const float* __restrict__ Ws, const float* __restrict__ Wn,
           const float* __restrict__ bias,
           float* __restrict__ out_in, int M) {
    const float* __restrict__ hs = hs_in ? hs_in : g_h1;
    float* __restrict__ out = out_in ? out_in : g_h1;

    __shared__ float As[2][128 * AST];
    __shared__ float Bs[2][16 * BST];

    int tid = threadIdx.x;
    int wid = tid >> 5, lane = tid & 31;
    int warp_m = (wid & 1) * 64;
    int warp_n = (wid >> 1) * 32;
    int base = blockIdx.x * 128;
    int qr = lane >> 2, qc = lane & 3;

    uint32_t as_base = (uint32_t)__cvta_generic_to_shared(&As[0][0]);
    uint32_t bs_base = (uint32_t)__cvta_generic_to_shared(&Bs[0][0]);

    int a_r0 = tid >> 2, a_s0 = (tid & 3) * 4;
    int a_r1 = (tid + 256) >> 2, a_s1 = a_s0;
    int b_r0 = tid >> 5, b_s0 = (tid & 31) * 4;
    int b_r1 = b_r0 + 8, b_s1 = b_s0;

    float acc[4][4][4];
#pragma unroll
    for (int a = 0; a < 4; a++)
#pragma unroll
        for (int b = 0; b < 4; b++)
#pragma unroll
            for (int c = 0; c < 4; c++) acc[a][b][c] = 0.f;

#define LOAD_CHUNK(c, buf)                                                      \
    {                                                                           \
        int p_ = (c) >> 3, kc_ = ((c) & 7) * 16;                                \
        const float* A_ = p_ ? g_mean : hs;                                     \
        const float* W_ = p_ ? Wn : Ws;                                         \
        uint32_t ab = as_base + (uint32_t)(buf) * 128 * AST * 4;                \
        uint32_t bb = bs_base + (uint32_t)(buf) * 16 * BST * 4;                 \
        cp16(ab + (a_r0 * AST + a_s0) * 4,                                      \
             A_ + (size_t)(base + a_r0) * F + kc_ + a_s0,                       \
             (base + a_r0 < M) ? 16 : 0);                                       \
        cp16(ab + (a_r1 * AST + a_s1) * 4,                                      \
             A_ + (size_t)(base + a_r1) * F + kc_ + a_s1,                       \
             (base + a_r1 < M) ? 16 : 0);                                       \
        cp16(bb + (b_r0 * BST + b_s0) * 4, W_ + (size_t)(kc_ + b_r0) * F + b_s0, 16); \
        cp16(bb + (b_r1 * BST + b_s1) * 4, W_ + (size_t)(kc_ + b_r1) * F + b_s1, 16); \
    }

    LOAD_CHUNK(0, 0);
    cp_commit();

    for (int c = 0; c < 16; ++c) {
        cp_wait<0>();
        __syncthreads();
        int buf = c & 1;
        if (c + 1 < 16) {
            LOAD_CHUNK(c + 1, buf ^ 1);
            cp_commit();
        }
        const float* as = As[buf];
        const float* bs = Bs[buf];
#pragma unroll
        for (int k8 = 0; k8 < 16; k8 += 8) {
            uint32_t bfr[4][2];
#pragma unroll
            for (int nt = 0; nt < 4; nt++) {
                int n = warp_n + nt * 8 + qr;
                bfr[nt][0] = cvt_tf32(bs[(k8 + qc) * BST + n]);
                bfr[nt][1] = cvt_tf32(bs[(k8 + qc + 4) * BST + n]);
            }
#pragma unroll
            for (int mt = 0; mt < 4; mt++) {
                int m = warp_m + mt * 16;
                uint32_t afr[4];
                afr[0] = cvt_tf32(as[(m + qr) * AST + k8 + qc]);
                afr[1] = cvt_tf32(as[(m + qr + 8) * AST + k8 + qc]);
                afr[2] = cvt_tf32(as[(m + qr) * AST + k8 + qc + 4]);
                afr[3] = cvt_tf32(as[(m + qr + 8) * AST + k8 + qc + 4]);
#pragma unroll
                for (int nt = 0; nt < 4; nt++)
                    mma_tf32(acc[mt][nt], afr, bfr[nt]);
            }
        }
        __syncthreads();
    }

#pragma unroll
    for (int nt = 0; nt < 4; nt++) {
        int col = warp_n + nt * 8 + 2 * qc;
        float b0 = bias[col], b1 = bias[col + 1];
#pragma unroll
        for (int mt = 0; mt < 4; mt++) {
#pragma unroll
            for (int h = 0; h < 2; h++) {
                int row = base + warp_m + mt * 16 + qr + h * 8;
                if (row < M) {
                    float v0 = acc[mt][nt][2 * h] + b0;
                    float v1 = acc[mt][nt][2 * h + 1] + b1;
                    if (LEAKY) {
                        v0 = v0 > 0.f ? v0 : 0.2f * v0;
                        v1 = v1 > 0.f ? v1 : 0.2f * v1;
                    }
                    float2 vv = make_float2(v0, v1);
                    *(float2*)(out + (size_t)row * F + col) = vv;
                    if (LEAKY) {   // layer 1: also write fp16 mirror for layer-2 gather
                        __half2 hv = __floats2half2_rn(v0, v1);
                        *(__half2*)(g_hhalf + (size_t)row * F + col) = hv;
                    }
                }
            }
        }
    }
#undef LOAD_CHUNK
}

// ---------------- launch ----------------------------------------------------
extern "C" void kernel_launch(void* const* d_in, const int* in_sizes, int n_in,
                              void* d_out, int out_size) {
    const float* emb = (const float*)d_in[0];
    const float* W1s = (const float*)d_in[1];
    const float* W1n = (const float*)d_in[2];
    const float* b1  = (const float*)d_in[3];
    const float* W2s = (const float*)d_in[4];
    const float* W2n = (const float*)d_in[5];
    const float* b2  = (const float*)d_in[6];
    const int*   edg = (const int*)d_in[7];

    int E = in_sizes[7] / 2;
    int M = in_sizes[0] / F;
    const int* src = edg;
    const int* dst = edg + E;
    float* out = (float*)d_out;

    int n = M + 1;
    int scanBlocks = (n + SCAN_TILE - 1) / SCAN_TILE;
    int n4 = M * F / 4;

    k_zero<<<(n + 255) / 256, 256>>>(n);
    k_hist<<<(E + 255) / 256, 256>>>(dst, E);
    k_cvt<<<(n4 + 255) / 256, 256>>>(emb, n4);   // fp16 mirror of emb
    k_scan1<<<scanBlocks, 1024>>>(n);
    k_scan3<<<scanBlocks, 1024>>>(n, scanBlocks);
    k_scatter<<<(E + 255) / 256, 256>>>(src, dst, E);

    int aggBlocks = (M * 32 + 255) / 256;
    int gemmBlocks = (M + 127) / 128;

    // layer 1
    k_agg<<<aggBlocks, 256>>>(M);
    k_gemm_mma<true><<<gemmBlocks, 256>>>(emb, W1s, W1n, b1, nullptr, M);

    // layer 2
    k_agg<<<aggBlocks, 256>>>(M);
    k_gemm_mma<false><<<gemmBlocks, 256>>>(nullptr, W2s, W2n, b2, out, M);
}

// round 6
// speedup vs baseline: 2.3049x; 1.2575x over previous
#include <cuda_runtime.h>
#include <cuda_fp16.h>
#include <cstdint>

#define NN 100000
#define NE 1600000
#define F  128

// ---------------- scratch (device globals: no allocation allowed) ----------
__device__ __align__(16) __half g_hhalf[(size_t)NN * F];   // 25.6 MB: emb/h1 fp16
__device__ __align__(16) __half g_mean16[(size_t)NN * F];  // 25.6 MB: mean fp16
__device__ __align__(16) __half g_w16[4][F * F];           // W^T fp16: [n][k]
__device__ int g_rowptr[NN + 1];
__device__ int g_fill[NN];
__device__ int g_csr[NE];
__device__ int g_tilesum[64];

// ---------------- fp16 mirror of emb ----------------------------------------
__global__ void k_cvt(const float* __restrict__ src, int n4) {
    int i = blockIdx.x * blockDim.x + threadIdx.x;
    if (i < n4) {
        float4 v = *(const float4*)(src + (size_t)i * 4);
        __half2 h0 = __floats2half2_rn(v.x, v.y);
        __half2 h1 = __floats2half2_rn(v.z, v.w);
        uint2 u;
        u.x = *(uint32_t*)&h0; u.y = *(uint32_t*)&h1;
        *(uint2*)(g_hhalf + (size_t)i * 4) = u;
    }
}

// ---------------- weights: fp16 + transpose [k][n] -> [n][k] -----------------
__global__ void k_cvtW(const float* __restrict__ w0, const float* __restrict__ w1,
                       const float* __restrict__ w2, const float* __restrict__ w3) {
    int i = blockIdx.x * blockDim.x + threadIdx.x;   // 0 .. 4*16384
    if (i >= 4 * F * F) return;
    int mat = i >> 14, idx = i & (F * F - 1);
    int k = idx >> 7, n = idx & 127;
    const float* w = mat == 0 ? w0 : mat == 1 ? w1 : mat == 2 ? w2 : w3;
    g_w16[mat][n * F + k] = __float2half_rn(w[idx]);
}

// ---------------- CSR build ------------------------------------------------
__global__ void k_zero(int n) {
    int i = blockIdx.x * blockDim.x + threadIdx.x;
    if (i < n) g_rowptr[i] = 0;
}

__global__ void k_hist(const int* __restrict__ dst, int E) {
    int i = blockIdx.x * blockDim.x + threadIdx.x;
    if (i < E) atomicAdd(&g_rowptr[dst[i] + 1], 1);
}

#define SCAN_TILE 4096
__global__ void __launch_bounds__(1024) k_scan1(int n) {
    __shared__ int ws[32];
    int t = threadIdx.x;
    int lane = t & 31, wid = t >> 5;
    int base = blockIdx.x * SCAN_TILE + t * 4;
    int v[4];
#pragma unroll
    for (int j = 0; j < 4; j++) v[j] = (base + j < n) ? g_rowptr[base + j] : 0;
    int s = v[0] + v[1] + v[2] + v[3];
    int sv = s;
#pragma unroll
    for (int o = 1; o < 32; o <<= 1) {
        int tmp = __shfl_up_sync(0xffffffffu, sv, o);
        if (lane >= o) sv += tmp;
    }
    if (lane == 31) ws[wid] = sv;
    __syncthreads();
    if (wid == 0) {
        int w = ws[lane];
#pragma unroll
        for (int o = 1; o < 32; o <<= 1) {
            int tmp = __shfl_up_sync(0xffffffffu, w, o);
            if (lane >= o) w += tmp;
        }
        ws[lane] = w;
    }
    __syncthreads();
    int excl = sv - s + (wid > 0 ? ws[wid - 1] : 0);
    int run = excl;
#pragma unroll
    for (int j = 0; j < 4; j++) {
        run += v[j];
        if (base + j < n) g_rowptr[base + j] = run;
    }
    if (t == 1023) g_tilesum[blockIdx.x] = ws[31];
}

__global__ void __launch_bounds__(1024) k_scan3(int n, int nblocks) {
    __shared__ int s_off;
    if (threadIdx.x < 32) {
        int lane = threadIdx.x;
        int v = (lane < nblocks) ? g_tilesum[lane] : 0;
        int sv = v;
#pragma unroll
        for (int o = 1; o < 32; o <<= 1) {
            int t = __shfl_up_sync(0xffffffffu, sv, o);
            if (lane >= o) sv += t;
        }
        if (lane == blockIdx.x) s_off = sv - v;
    }
    __syncthreads();
    int off = s_off;
    int base = blockIdx.x * SCAN_TILE + threadIdx.x * 4;
#pragma unroll
    for (int j = 0; j < 4; j++) {
        int i = base + j;
        if (i < n) {
            int val = g_rowptr[i] + off;
            g_rowptr[i] = val;
            if (i < n - 1) g_fill[i] = val;
        }
    }
}

__global__ void k_scatter(const int* __restrict__ src, const int* __restrict__ dst, int E) {
    int i = blockIdx.x * blockDim.x + threadIdx.x;
    if (i < E) {
        int pos = atomicAdd(&g_fill[dst[i]], 1);
        g_csr[pos] = src[i];
    }
}

// ---------------- mean aggregation: warp per node, fp16 gather + fp16 out ---
__global__ void k_agg(int M) {
    int node = (blockIdx.x * blockDim.x + threadIdx.x) >> 5;
    if (node >= M) return;
    int lane = threadIdx.x & 31;
    int s0 = g_rowptr[node], s1 = g_rowptr[node + 1];
    int deg = s1 - s0;
    float4 acc = make_float4(0.f, 0.f, 0.f, 0.f);
    int c = s0;
    while (c < s1) {
        int cnt = min(32, s1 - c);
        int idx = 0;
        if (lane < cnt) idx = g_csr[c + lane];
        int j = 0;
        for (; j + 8 <= cnt; j += 8) {
            uint2 u[8];
#pragma unroll
            for (int v = 0; v < 8; v++) {
                int a = __shfl_sync(0xffffffffu, idx, j + v);
                u[v] = *(const uint2*)(g_hhalf + (size_t)a * F + lane * 4);
            }
#pragma unroll
            for (int v = 0; v < 8; v++) {
                __half2 h0 = *(__half2*)&u[v].x, h1 = *(__half2*)&u[v].y;
                float2 f0 = __half22float2(h0), f1 = __half22float2(h1);
                acc.x += f0.x; acc.y += f0.y; acc.z += f1.x; acc.w += f1.y;
            }
        }
        for (; j < cnt; j++) {
            int a = __shfl_sync(0xffffffffu, idx, j);
            uint2 u = *(const uint2*)(g_hhalf + (size_t)a * F + lane * 4);
            __half2 h0 = *(__half2*)&u.x, h1 = *(__half2*)&u.y;
            float2 f0 = __half22float2(h0), f1 = __half22float2(h1);
            acc.x += f0.x; acc.y += f0.y; acc.z += f1.x; acc.w += f1.y;
        }
        c += cnt;
    }
    float inv = 1.0f / (float)max(deg, 1);
    __half2 m0 = __floats2half2_rn(acc.x * inv, acc.y * inv);
    __half2 m1 = __floats2half2_rn(acc.z * inv, acc.w * inv);
    uint2 u;
    u.x = *(uint32_t*)&m0; u.y = *(uint32_t*)&m1;
    *(uint2*)(g_mean16 + (size_t)node * F + lane * 4) = u;
}

// ---------------- mma / cp.async helpers -------------------------------------
__device__ __forceinline__ void mma_f16(float* c, const uint32_t* a, const uint32_t* b) {
    asm volatile(
        "mma.sync.aligned.m16n8k16.row.col.f32.f16.f16.f32 "
        "{%0,%1,%2,%3}, {%4,%5,%6,%7}, {%8,%9}, {%0,%1,%2,%3};"
        : "+f"(c[0]), "+f"(c[1]), "+f"(c[2]), "+f"(c[3])
        : "r"(a[0]), "r"(a[1]), "r"(a[2]), "r"(a[3]), "r"(b[0]), "r"(b[1]));
}

__device__ __forceinline__ void cp16(uint32_t dst, const void* src, int sz) {
    asm volatile("cp.async.cg.shared.global [%0], [%1], 16, %2;\n"
                 :: "r"(dst), "l"(src), "r"(sz));
}
__device__ __forceinline__ void cp_commit() {
    asm volatile("cp.async.commit_group;\n" ::: "memory");
}
template <int N>
__device__ __forceinline__ void cp_wait() {
    asm volatile("cp.async.wait_group %0;\n" :: "n"(N) : "memory");
}

// ---------------- fused dual-GEMM fp16, cp.async double-buffered -------------
// out = hself @ Ws^T' + mean @ Wn^T' + b. CTA 128x128, BK=32 (halves).
// Smem tiles stored with row stride 20 words (40 halves) -> conflict-free frags.
#define STW 20   // words per row
template <bool LAYER1>
__global__ void __launch_bounds__(256)
k_gemm_mma(const float* __restrict__ bias, float* __restrict__ out, int M) {
    const __half* __restrict__ ws = g_w16[LAYER1 ? 0 : 2];
    const __half* __restrict__ wn = g_w16[LAYER1 ? 1 : 3];

    __shared__ uint32_t As[2][128 * STW];   // 20 KB
    __shared__ uint32_t Bs[2][128 * STW];   // 20 KB

    int tid = threadIdx.x;
    int wid = tid >> 5, lane = tid & 31;
    int warp_m = (wid & 1) * 64;
    int warp_n = (wid >> 1) * 32;
    int base = blockIdx.x * 128;
    int qr = lane >> 2, qc = lane & 3;

    uint32_t as_base = (uint32_t)__cvta_generic_to_shared(&As[0][0]);
    uint32_t bs_base = (uint32_t)__cvta_generic_to_shared(&Bs[0][0]);

    // staging map: 512 cp16 per tile, 2 per thread. idx -> row = idx>>2, seg = (idx&3)*8 halves
    int r0 = tid >> 1;                 // rows 0..127, two threads per row
    int s0h = (tid & 1) * 16;          // halves 0 or 16
    // each thread does segments s0h and s0h+8
    float acc[4][4][4];
#pragma unroll
    for (int a = 0; a < 4; a++)
#pragma unroll
        for (int b = 0; b < 4; b++)
#pragma unroll
            for (int c = 0; c < 4; c++) acc[a][b][c] = 0.f;

    // chunk c in [0,8): pass p=c>>2 selects (A,W); kc=(c&3)*32 halves
#define LOAD_CHUNK(c, buf)                                                        \
    {                                                                             \
        int p_ = (c) >> 2, kc_ = ((c) & 3) * 32;                                  \
        const __half* A_ = p_ ? g_mean16 : g_hhalf;                               \
        const __half* W_ = p_ ? wn : ws;                                          \
        uint32_t ab = as_base + (uint32_t)(buf) * 128 * STW * 4;                  \
        uint32_t bb = bs_base + (uint32_t)(buf) * 128 * STW * 4;                  \
        int ok = (base + r0 < M) ? 16 : 0;                                        \
        cp16(ab + (r0 * STW) * 4 + s0h * 2,                                       \
             A_ + (size_t)(base + r0) * F + kc_ + s0h, ok);                       \
        cp16(ab + (r0 * STW) * 4 + (s0h + 8) * 2,                                 \
             A_ + (size_t)(base + r0) * F + kc_ + s0h + 8, ok);                   \
        cp16(bb + (r0 * STW) * 4 + s0h * 2,                                       \
             W_ + (size_t)r0 * F + kc_ + s0h, 16);                                \
        cp16(bb + (r0 * STW) * 4 + (s0h + 8) * 2,                                 \
             W_ + (size_t)r0 * F + kc_ + s0h + 8, 16);                            \
    }

    LOAD_CHUNK(0, 0);
    cp_commit();

    for (int c = 0; c < 8; ++c) {
        cp_wait<0>();
        __syncthreads();
        int buf = c & 1;
        if (c + 1 < 8) {
            LOAD_CHUNK(c + 1, buf ^ 1);
            cp_commit();
        }
        const uint32_t* as = As[buf];
        const uint32_t* bs = Bs[buf];
#pragma unroll
        for (int s = 0; s < 2; s++) {       // two k16 steps per 32-chunk
            int kw = s * 8;
            uint32_t bfr[4][2];
#pragma unroll
            for (int nt = 0; nt < 4; nt++) {
                int n = warp_n + nt * 8 + qr;
                bfr[nt][0] = bs[n * STW + kw + qc];
                bfr[nt][1] = bs[n * STW + kw + qc + 4];
            }
#pragma unroll
            for (int mt = 0; mt < 4; mt++) {
                int m = warp_m + mt * 16;
                uint32_t afr[4];
                afr[0] = as[(m + qr) * STW + kw + qc];
                afr[1] = as[(m + qr + 8) * STW + kw + qc];
                afr[2] = as[(m + qr) * STW + kw + qc + 4];
                afr[3] = as[(m + qr + 8) * STW + kw + qc + 4];
#pragma unroll
                for (int nt = 0; nt < 4; nt++)
                    mma_f16(acc[mt][nt], afr, bfr[nt]);
            }
        }
        __syncthreads();
    }

    // epilogue
#pragma unroll
    for (int nt = 0; nt < 4; nt++) {
        int col = warp_n + nt * 8 + 2 * qc;
        float b0 = bias[col], b1 = bias[col + 1];
#pragma unroll
        for (int mt = 0; mt < 4; mt++) {
#pragma unroll
            for (int h = 0; h < 2; h++) {
                int row = base + warp_m + mt * 16 + qr + h * 8;
                if (row < M) {
                    float v0 = acc[mt][nt][2 * h] + b0;
                    float v1 = acc[mt][nt][2 * h + 1] + b1;
                    if (LAYER1) {
                        v0 = v0 > 0.f ? v0 : 0.2f * v0;
                        v1 = v1 > 0.f ? v1 : 0.2f * v1;
                        __half2 hv = __floats2half2_rn(v0, v1);
                        *(__half2*)(g_hhalf + (size_t)row * F + col) = hv;
                    } else {
                        float2 vv = make_float2(v0, v1);
                        *(float2*)(out + (size_t)row * F + col) = vv;
                    }
                }
            }
        }
    }
#undef LOAD_CHUNK
}

// ---------------- launch ----------------------------------------------------
extern "C" void kernel_launch(void* const* d_in, const int* in_sizes, int n_in,
                              void* d_out, int out_size) {
    const float* emb = (const float*)d_in[0];
    const float* W1s = (const float*)d_in[1];
    const float* W1n = (const float*)d_in[2];
    const float* b1  = (const float*)d_in[3];
    const float* W2s = (const float*)d_in[4];
    const float* W2n = (const float*)d_in[5];
    const float* b2  = (const float*)d_in[6];
    const int*   edg = (const int*)d_in[7];

    int E = in_sizes[7] / 2;
    int M = in_sizes[0] / F;
    const int* src = edg;
    const int* dst = edg + E;
    float* out = (float*)d_out;

    int n = M + 1;
    int scanBlocks = (n + SCAN_TILE - 1) / SCAN_TILE;
    int n4 = M * F / 4;

    k_zero<<<(n + 255) / 256, 256>>>(n);
    k_hist<<<(E + 255) / 256, 256>>>(dst, E);
    k_cvt<<<(n4 + 255) / 256, 256>>>(emb, n4);
    k_cvtW<<<(4 * F * F + 255) / 256, 256>>>(W1s, W1n, W2s, W2n);
    k_scan1<<<scanBlocks, 1024>>>(n);
    k_scan3<<<scanBlocks, 1024>>>(n, scanBlocks);
    k_scatter<<<(E + 255) / 256, 256>>>(src, dst, E);

    int aggBlocks = (M * 32 + 255) / 256;
    int gemmBlocks = (M + 127) / 128;

    // layer 1: agg(emb16) -> mean16 ; h1(fp16) = leaky(emb@W1s + mean@W1n + b1)
    k_agg<<<aggBlocks, 256>>>(M);
    k_gemm_mma<true><<<gemmBlocks, 256>>>(b1, nullptr, M);

    // layer 2: agg(h1) -> mean16 ; out = h1@W2s + mean@W2n + b2
    k_agg<<<aggBlocks, 256>>>(M);
    k_gemm_mma<false><<<gemmBlocks, 256>>>(b2, out, M);
}

// round 7
// speedup vs baseline: 2.3948x; 1.0390x over previous
#include <cuda_runtime.h>
#include <cuda_fp16.h>
#include <cstdint>

#define NN 100000
#define NE 1600000
#define F  128

// ---------------- scratch (device globals: no allocation allowed) ----------
__device__ __align__(16) __half g_hhalf[(size_t)NN * F];   // 25.6 MB: emb/h1 fp16
__device__ __align__(16) __half g_mean16[(size_t)NN * F];  // 25.6 MB: mean fp16
__device__ __align__(16) __half g_w16[4][F * F];           // W^T fp16: [n][k]
__device__ int g_rowptr[NN + 1];
__device__ int g_fill[NN];
__device__ int g_csr[NE];
__device__ int g_tilesum[64];

// ---------------- zero rowptr -------------------------------------------------
__global__ void k_zero(int n) {
    int i = blockIdx.x * blockDim.x + threadIdx.x;
    if (i < n) g_rowptr[i] = 0;
}

// ---------------- fused prep: hist || emb->fp16 || weights->fp16^T ------------
__global__ void k_prep(const float* __restrict__ emb,
                       const float* __restrict__ w0, const float* __restrict__ w1,
                       const float* __restrict__ w2, const float* __restrict__ w3,
                       const int* __restrict__ dst, int E, int n4,
                       int histBlocks, int cvtBlocks) {
    int b = blockIdx.x;
    int t = threadIdx.x;
    if (b < histBlocks) {                       // edge histogram
        int i = b * 256 + t;
        if (i < E) atomicAdd(&g_rowptr[dst[i] + 1], 1);
    } else if (b < histBlocks + cvtBlocks) {    // emb -> fp16 mirror
        int i = (b - histBlocks) * 256 + t;
        if (i < n4) {
            float4 v = *(const float4*)(emb + (size_t)i * 4);
            __half2 h0 = __floats2half2_rn(v.x, v.y);
            __half2 h1 = __floats2half2_rn(v.z, v.w);
            uint2 u;
            u.x = *(uint32_t*)&h0; u.y = *(uint32_t*)&h1;
            *(uint2*)(g_hhalf + (size_t)i * 4) = u;
        }
    } else {                                    // weights: fp16 + transpose
        int i = (b - histBlocks - cvtBlocks) * 256 + t;
        if (i < 4 * F * F) {
            int mat = i >> 14, idx = i & (F * F - 1);
            int k = idx >> 7, n = idx & 127;
            const float* w = mat == 0 ? w0 : mat == 1 ? w1 : mat == 2 ? w2 : w3;
            g_w16[mat][n * F + k] = __float2half_rn(w[idx]);
        }
    }
}

// ---------------- parallel scan ------------------------------------------------
#define SCAN_TILE 4096
__global__ void __launch_bounds__(1024) k_scan1(int n) {
    __shared__ int ws[32];
    int t = threadIdx.x;
    int lane = t & 31, wid = t >> 5;
    int base = blockIdx.x * SCAN_TILE + t * 4;
    int v[4];
#pragma unroll
    for (int j = 0; j < 4; j++) v[j] = (base + j < n) ? g_rowptr[base + j] : 0;
    int s = v[0] + v[1] + v[2] + v[3];
    int sv = s;
#pragma unroll
    for (int o = 1; o < 32; o <<= 1) {
        int tmp = __shfl_up_sync(0xffffffffu, sv, o);
        if (lane >= o) sv += tmp;
    }
    if (lane == 31) ws[wid] = sv;
    __syncthreads();
    if (wid == 0) {
        int w = ws[lane];
#pragma unroll
        for (int o = 1; o < 32; o <<= 1) {
            int tmp = __shfl_up_sync(0xffffffffu, w, o);
            if (lane >= o) w += tmp;
        }
        ws[lane] = w;
    }
    __syncthreads();
    int excl = sv - s + (wid > 0 ? ws[wid - 1] : 0);
    int run = excl;
#pragma unroll
    for (int j = 0; j < 4; j++) {
        run += v[j];
        if (base + j < n) g_rowptr[base + j] = run;
    }
    if (t == 1023) g_tilesum[blockIdx.x] = ws[31];
}

__global__ void __launch_bounds__(1024) k_scan3(int n, int nblocks) {
    __shared__ int s_off;
    if (threadIdx.x < 32) {
        int lane = threadIdx.x;
        int v = (lane < nblocks) ? g_tilesum[lane] : 0;
        int sv = v;
#pragma unroll
        for (int o = 1; o < 32; o <<= 1) {
            int t = __shfl_up_sync(0xffffffffu, sv, o);
            if (lane >= o) sv += t;
        }
        if (lane == blockIdx.x) s_off = sv - v;
    }
    __syncthreads();
    int off = s_off;
    int base = blockIdx.x * SCAN_TILE + threadIdx.x * 4;
#pragma unroll
    for (int j = 0; j < 4; j++) {
        int i = base + j;
        if (i < n) {
            int val = g_rowptr[i] + off;
            g_rowptr[i] = val;
            if (i < n - 1) g_fill[i] = val;
        }
    }
}

__global__ void k_scatter(const int* __restrict__ src, const int* __restrict__ dst, int E) {
    int i = blockIdx.x * blockDim.x + threadIdx.x;
    if (i < E) {
        int pos = atomicAdd(&g_fill[dst[i]], 1);
        g_csr[pos] = src[i];
    }
}

// ---------------- mean aggregation: warp per node, fp16 gather + fp16 out ---
__global__ void k_agg(int M) {
    int node = (blockIdx.x * blockDim.x + threadIdx.x) >> 5;
    if (node >= M) return;
    int lane = threadIdx.x & 31;
    int s0 = g_rowptr[node], s1 = g_rowptr[node + 1];
    int deg = s1 - s0;
    float4 acc = make_float4(0.f, 0.f, 0.f, 0.f);
    int c = s0;
    while (c < s1) {
        int cnt = min(32, s1 - c);
        int idx = 0;
        if (lane < cnt) idx = g_csr[c + lane];
        int j = 0;
        for (; j + 8 <= cnt; j += 8) {
            uint2 u[8];
#pragma unroll
            for (int v = 0; v < 8; v++) {
                int a = __shfl_sync(0xffffffffu, idx, j + v);
                u[v] = *(const uint2*)(g_hhalf + (size_t)a * F + lane * 4);
            }
#pragma unroll
            for (int v = 0; v < 8; v++) {
                __half2 h0 = *(__half2*)&u[v].x, h1 = *(__half2*)&u[v].y;
                float2 f0 = __half22float2(h0), f1 = __half22float2(h1);
                acc.x += f0.x; acc.y += f0.y; acc.z += f1.x; acc.w += f1.y;
            }
        }
        for (; j < cnt; j++) {
            int a = __shfl_sync(0xffffffffu, idx, j);
            uint2 u = *(const uint2*)(g_hhalf + (size_t)a * F + lane * 4);
            __half2 h0 = *(__half2*)&u.x, h1 = *(__half2*)&u.y;
            float2 f0 = __half22float2(h0), f1 = __half22float2(h1);
            acc.x += f0.x; acc.y += f0.y; acc.z += f1.x; acc.w += f1.y;
        }
        c += cnt;
    }
    float inv = 1.0f / (float)max(deg, 1);
    __half2 m0 = __floats2half2_rn(acc.x * inv, acc.y * inv);
    __half2 m1 = __floats2half2_rn(acc.z * inv, acc.w * inv);
    uint2 u;
    u.x = *(uint32_t*)&m0; u.y = *(uint32_t*)&m1;
    *(uint2*)(g_mean16 + (size_t)node * F + lane * 4) = u;
}

// ---------------- mma / cp.async helpers -------------------------------------
__device__ __forceinline__ void mma_f16(float* c, const uint32_t* a, const uint32_t* b) {
    asm volatile(
        "mma.sync.aligned.m16n8k16.row.col.f32.f16.f16.f32 "
        "{%0,%1,%2,%3}, {%4,%5,%6,%7}, {%8,%9}, {%0,%1,%2,%3};"
        : "+f"(c[0]), "+f"(c[1]), "+f"(c[2]), "+f"(c[3])
        : "r"(a[0]), "r"(a[1]), "r"(a[2]), "r"(a[3]), "r"(b[0]), "r"(b[1]));
}

__device__ __forceinline__ void cp16(uint32_t dst, const void* src, int sz) {
    asm volatile("cp.async.cg.shared.global [%0], [%1], 16, %2;\n"
                 :: "r"(dst), "l"(src), "r"(sz));
}
__device__ __forceinline__ void cp_commit() {
    asm volatile("cp.async.commit_group;\n" ::: "memory");
}
template <int N>
__device__ __forceinline__ void cp_wait() {
    asm volatile("cp.async.wait_group %0;\n" :: "n"(N) : "memory");
}

// ---------------- fused dual-GEMM fp16, 3-stage cp.async pipeline ------------
// out = hself @ Ws^T' + mean @ Wn^T' + b. CTA 128x128, BK=32 halves, 8 chunks.
// Dynamic smem: 3 stages x (A 10KB + B 10KB) = 60KB.
#define STW 20            // words per smem row
#define STAGE_W (128 * STW)   // words per stage per matrix (2560)
template <bool LAYER1>
__global__ void __launch_bounds__(256, 2)
k_gemm_mma(const float* __restrict__ bias, float* __restrict__ out, int M) {
    const __half* __restrict__ ws = g_w16[LAYER1 ? 0 : 2];
    const __half* __restrict__ wn = g_w16[LAYER1 ? 1 : 3];

    extern __shared__ uint32_t smem[];
    uint32_t smem_u32 = (uint32_t)__cvta_generic_to_shared(smem);

    int tid = threadIdx.x;
    int wid = tid >> 5, lane = tid & 31;
    int warp_m = (wid & 1) * 64;
    int warp_n = (wid >> 1) * 32;
    int base = blockIdx.x * 128;
    int qr = lane >> 2, qc = lane & 3;

    int r0 = tid >> 1;                 // rows 0..127, two threads per row
    int s0h = (tid & 1) * 16;          // halves 0 or 16

    float acc[4][4][4];
#pragma unroll
    for (int a = 0; a < 4; a++)
#pragma unroll
        for (int b = 0; b < 4; b++)
#pragma unroll
            for (int c = 0; c < 4; c++) acc[a][b][c] = 0.f;

    // chunk c in [0,8): pass p=c>>2 selects (A,W); kc=(c&3)*32 halves
#define LOAD_CHUNK(c, stage)                                                      \
    {                                                                             \
        int p_ = (c) >> 2, kc_ = ((c) & 3) * 32;                                  \
        const __half* A_ = p_ ? g_mean16 : g_hhalf;                               \
        const __half* W_ = p_ ? wn : ws;                                          \
        uint32_t ab = smem_u32 + (uint32_t)(stage) * STAGE_W * 4;                 \
        uint32_t bb = smem_u32 + (3u + (uint32_t)(stage)) * STAGE_W * 4;          \
        int ok = (base + r0 < M) ? 16 : 0;                                        \
        cp16(ab + (r0 * STW) * 4 + s0h * 2,                                       \
             A_ + (size_t)(base + r0) * F + kc_ + s0h, ok);                       \
        cp16(ab + (r0 * STW) * 4 + (s0h + 8) * 2,                                 \
             A_ + (size_t)(base + r0) * F + kc_ + s0h + 8, ok);                   \
        cp16(bb + (r0 * STW) * 4 + s0h * 2,                                       \
             W_ + (size_t)r0 * F + kc_ + s0h, 16);                                \
        cp16(bb + (r0 * STW) * 4 + (s0h + 8) * 2,                                 \
             W_ + (size_t)r0 * F + kc_ + s0h + 8, 16);                            \
    }

    LOAD_CHUNK(0, 0); cp_commit();
    LOAD_CHUNK(1, 1); cp_commit();

    for (int c = 0; c < 8; ++c) {
        cp_wait<1>();              // chunk c resident
        __syncthreads();           // visible to all; prev MMA done -> stage free
        if (c + 2 < 8) {
            LOAD_CHUNK(c + 2, (c + 2) % 3);
            cp_commit();
        }
        int stg = c % 3;
        const uint32_t* as = smem + stg * STAGE_W;
        const uint32_t* bs = smem + (3 + stg) * STAGE_W;
#pragma unroll
        for (int s = 0; s < 2; s++) {       // two k16 steps per 32-chunk
            int kw = s * 8;
            uint32_t bfr[4][2];
#pragma unroll
            for (int nt = 0; nt < 4; nt++) {
                int n = warp_n + nt * 8 + qr;
                bfr[nt][0] = bs[n * STW + kw + qc];
                bfr[nt][1] = bs[n * STW + kw + qc + 4];
            }
#pragma unroll
            for (int mt = 0; mt < 4; mt++) {
                int m = warp_m + mt * 16;
                uint32_t afr[4];
                afr[0] = as[(m + qr) * STW + kw + qc];
                afr[1] = as[(m + qr + 8) * STW + kw + qc];
                afr[2] = as[(m + qr) * STW + kw + qc + 4];
                afr[3] = as[(m + qr + 8) * STW + kw + qc + 4];
#pragma unroll
                for (int nt = 0; nt < 4; nt++)
                    mma_f16(acc[mt][nt], afr, bfr[nt]);
            }
        }
    }

    // epilogue
#pragma unroll
    for (int nt = 0; nt < 4; nt++) {
        int col = warp_n + nt * 8 + 2 * qc;
        float b0 = bias[col], b1 = bias[col + 1];
#pragma unroll
        for (int mt = 0; mt < 4; mt++) {
#pragma unroll
            for (int h = 0; h < 2; h++) {
                int row = base + warp_m + mt * 16 + qr + h * 8;
                if (row < M) {
                    float v0 = acc[mt][nt][2 * h] + b0;
                    float v1 = acc[mt][nt][2 * h + 1] + b1;
                    if (LAYER1) {
                        v0 = v0 > 0.f ? v0 : 0.2f * v0;
                        v1 = v1 > 0.f ? v1 : 0.2f * v1;
                        __half2 hv = __floats2half2_rn(v0, v1);
                        *(__half2*)(g_hhalf + (size_t)row * F + col) = hv;
                    } else {
                        float2 vv = make_float2(v0, v1);
                        *(float2*)(out + (size_t)row * F + col) = vv;
                    }
                }
            }
        }
    }
#undef LOAD_CHUNK
}

// ---------------- launch ----------------------------------------------------
extern "C" void kernel_launch(void* const* d_in, const int* in_sizes, int n_in,
                              void* d_out, int out_size) {
    const float* emb = (const float*)d_in[0];
    const float* W1s = (const float*)d_in[1];
    const float* W1n = (const float*)d_in[2];
    const float* b1  = (const float*)d_in[3];
    const float* W2s = (const float*)d_in[4];
    const float* W2n = (const float*)d_in[5];
    const float* b2  = (const float*)d_in[6];
    const int*   edg = (const int*)d_in[7];

    int E = in_sizes[7] / 2;
    int M = in_sizes[0] / F;
    const int* src = edg;
    const int* dst = edg + E;
    float* out = (float*)d_out;

    int n = M + 1;
    int scanBlocks = (n + SCAN_TILE - 1) / SCAN_TILE;
    int n4 = M * F / 4;
    int histBlocks = (E + 255) / 256;
    int cvtBlocks = (n4 + 255) / 256;
    int wBlocks = (4 * F * F + 255) / 256;

    const int GEMM_SMEM = 6 * STAGE_W * 4;   // 61440 B
    cudaFuncSetAttribute(k_gemm_mma<true>,
                         cudaFuncAttributeMaxDynamicSharedMemorySize, GEMM_SMEM);
    cudaFuncSetAttribute(k_gemm_mma<false>,
                         cudaFuncAttributeMaxDynamicSharedMemorySize, GEMM_SMEM);

    k_zero<<<(n + 255) / 256, 256>>>(n);
    k_prep<<<histBlocks + cvtBlocks + wBlocks, 256>>>(
        emb, W1s, W1n, W2s, W2n, dst, E, n4, histBlocks, cvtBlocks);
    k_scan1<<<scanBlocks, 1024>>>(n);
    k_scan3<<<scanBlocks, 1024>>>(n, scanBlocks);
    k_scatter<<<(E + 255) / 256, 256>>>(src, dst, E);

    int aggBlocks = (M * 32 + 255) / 256;
    int gemmBlocks = (M + 127) / 128;

    // layer 1
    k_agg<<<aggBlocks, 256>>>(M);
    k_gemm_mma<true><<<gemmBlocks, 256, GEMM_SMEM>>>(b1, nullptr, M);

    // layer 2
    k_agg<<<aggBlocks, 256>>>(M);
    k_gemm_mma<false><<<gemmBlocks, 256, GEMM_SMEM>>>(b2, out, M);
}

// round 9
// speedup vs baseline: 2.4421x; 1.0197x over previous
#include <cuda_runtime.h>
#include <cuda_fp16.h>
#include <cstdint>

#define NN 100000
#define NE 1600000
#define F  128

// ---------------- scratch (device globals: no allocation allowed) ----------
__device__ __align__(16) __half g_hhalf[(size_t)NN * F];   // 25.6 MB: emb/h1 fp16
__device__ __align__(16) __half g_mean16[(size_t)NN * F];  // 25.6 MB: mean fp16
__device__ __align__(16) __half g_w16[4][F * F];           // W^T fp16: [n][k]
__device__ int g_rowptr[NN + 1];
__device__ int g_fill[NN];
__device__ int g_csr[NE];
__device__ int g_tilesum[64];

// ---------------- fused prep: hist || emb->fp16 || weights->fp16^T ------------
__global__ void k_prep(const float* __restrict__ emb,
                       const float* __restrict__ w0, const float* __restrict__ w1,
                       const float* __restrict__ w2, const float* __restrict__ w3,
                       const int* __restrict__ dst, int E, int n4,
                       int histBlocks, int cvtBlocks) {
    int b = blockIdx.x;
    int t = threadIdx.x;
    if (b < histBlocks) {                       // edge histogram
        int i = b * 256 + t;
        if (i < E) atomicAdd(&g_rowptr[dst[i] + 1], 1);
    } else if (b < histBlocks + cvtBlocks) {    // emb -> fp16 mirror
        int i = (b - histBlocks) * 256 + t;
        if (i < n4) {
            float4 v = *(const float4*)(emb + (size_t)i * 4);
            __half2 h0 = __floats2half2_rn(v.x, v.y);
            __half2 h1 = __floats2half2_rn(v.z, v.w);
            uint2 u;
            u.x = *(uint32_t*)&h0; u.y = *(uint32_t*)&h1;
            *(uint2*)(g_hhalf + (size_t)i * 4) = u;
        }
    } else {                                    // weights: fp16 + transpose
        int i = (b - histBlocks - cvtBlocks) * 256 + t;
        if (i < 4 * F * F) {
            int mat = i >> 14, idx = i & (F * F - 1);
            int k = idx >> 7, n = idx & 127;
            const float* w = mat == 0 ? w0 : mat == 1 ? w1 : mat == 2 ? w2 : w3;
            g_w16[mat][n * F + k] = __float2half_rn(w[idx]);
        }
    }
}

// ---------------- parallel scan ------------------------------------------------
#define SCAN_TILE 4096
__global__ void __launch_bounds__(1024) k_scan1(int n) {
    __shared__ int ws[32];
    int t = threadIdx.x;
    int lane = t & 31, wid = t >> 5;
    int base = blockIdx.x * SCAN_TILE + t * 4;
    int v[4];
#pragma unroll
    for (int j = 0; j < 4; j++) v[j] = (base + j < n) ? g_rowptr[base + j] : 0;
    int s = v[0] + v[1] + v[2] + v[3];
    int sv = s;
#pragma unroll
    for (int o = 1; o < 32; o <<= 1) {
        int tmp = __shfl_up_sync(0xffffffffu, sv, o);
        if (lane >= o) sv += tmp;
    }
    if (lane == 31) ws[wid] = sv;
    __syncthreads();
    if (wid == 0) {
        int w = ws[lane];
#pragma unroll
        for (int o = 1; o < 32; o <<= 1) {
            int tmp = __shfl_up_sync(0xffffffffu, w, o);
            if (lane >= o) w += tmp;
        }
        ws[lane] = w;
    }
    __syncthreads();
    int excl = sv - s + (wid > 0 ? ws[wid - 1] : 0);
    int run = excl;
#pragma unroll
    for (int j = 0; j < 4; j++) {
        run += v[j];
        if (base + j < n) g_rowptr[base + j] = run;
    }
    if (t == 1023) g_tilesum[blockIdx.x] = ws[31];
}

__global__ void __launch_bounds__(1024) k_scan3(int n, int nblocks) {
    __shared__ int s_off;
    if (threadIdx.x < 32) {
        int lane = threadIdx.x;
        int v = (lane < nblocks) ? g_tilesum[lane] : 0;
        int sv = v;
#pragma unroll
        for (int o = 1; o < 32; o <<= 1) {
            int t = __shfl_up_sync(0xffffffffu, sv, o);
            if (lane >= o) sv += t;
        }
        if (lane == blockIdx.x) s_off = sv - v;
    }
    __syncthreads();
    int off = s_off;
    int base = blockIdx.x * SCAN_TILE + threadIdx.x * 4;
#pragma unroll
    for (int j = 0; j < 4; j++) {
        int i = base + j;
        if (i < n) {
            int val = g_rowptr[i] + off;
            g_rowptr[i] = val;
            if (i < n - 1) g_fill[i] = val;
        }
    }
}

__global__ void k_scatter(const int* __restrict__ src, const int* __restrict__ dst, int E) {
    int i = blockIdx.x * blockDim.x + threadIdx.x;
    if (i < E) {
        int pos = atomicAdd(&g_fill[dst[i]], 1);
        g_csr[pos] = src[i];
    }
}

// ---------------- mean aggregation: warp per node, fp16 gather + fp16 out ---
__global__ void k_agg(int M) {
    int node = (blockIdx.x * blockDim.x + threadIdx.x) >> 5;
    if (node >= M) return;
    int lane = threadIdx.x & 31;
    int s0 = g_rowptr[node], s1 = g_rowptr[node + 1];
    int deg = s1 - s0;
    float4 acc = make_float4(0.f, 0.f, 0.f, 0.f);
    int c = s0;
    while (c < s1) {
        int cnt = min(32, s1 - c);
        int idx = 0;
        if (lane < cnt) idx = g_csr[c + lane];
        int j = 0;
        for (; j + 8 <= cnt; j += 8) {
            uint2 u[8];
#pragma unroll
            for (int v = 0; v < 8; v++) {
                int a = __shfl_sync(0xffffffffu, idx, j + v);
                u[v] = *(const uint2*)(g_hhalf + (size_t)a * F + lane * 4);
            }
#pragma unroll
            for (int v = 0; v < 8; v++) {
                __half2 h0 = *(__half2*)&u[v].x, h1 = *(__half2*)&u[v].y;
                float2 f0 = __half22float2(h0), f1 = __half22float2(h1);
                acc.x += f0.x; acc.y += f0.y; acc.z += f1.x; acc.w += f1.y;
            }
        }
        for (; j < cnt; j++) {
            int a = __shfl_sync(0xffffffffu, idx, j);
            uint2 u = *(const uint2*)(g_hhalf + (size_t)a * F + lane * 4);
            __half2 h0 = *(__half2*)&u.x, h1 = *(__half2*)&u.y;
            float2 f0 = __half22float2(h0), f1 = __half22float2(h1);
            acc.x += f0.x; acc.y += f0.y; acc.z += f1.x; acc.w += f1.y;
        }
        c += cnt;
    }
    float inv = 1.0f / (float)max(deg, 1);
    __half2 m0 = __floats2half2_rn(acc.x * inv, acc.y * inv);
    __half2 m1 = __floats2half2_rn(acc.z * inv, acc.w * inv);
    uint2 u;
    u.x = *(uint32_t*)&m0; u.y = *(uint32_t*)&m1;
    *(uint2*)(g_mean16 + (size_t)node * F + lane * 4) = u;
}

// ---------------- mma / cp.async / ldmatrix helpers ---------------------------
__device__ __forceinline__ void mma_f16(float* c, const uint32_t* a, const uint32_t* b) {
    asm volatile(
        "mma.sync.aligned.m16n8k16.row.col.f32.f16.f16.f32 "
        "{%0,%1,%2,%3}, {%4,%5,%6,%7}, {%8,%9}, {%0,%1,%2,%3};"
        : "+f"(c[0]), "+f"(c[1]), "+f"(c[2]), "+f"(c[3])
        : "r"(a[0]), "r"(a[1]), "r"(a[2]), "r"(a[3]), "r"(b[0]), "r"(b[1]));
}

__device__ __forceinline__ void ldsm4(uint32_t& r0, uint32_t& r1, uint32_t& r2,
                                      uint32_t& r3, uint32_t addr) {
    asm volatile("ldmatrix.sync.aligned.m8n8.x4.shared.b16 {%0,%1,%2,%3}, [%4];"
                 : "=r"(r0), "=r"(r1), "=r"(r2), "=r"(r3) : "r"(addr));
}

__device__ __forceinline__ void cp16(uint32_t dst, const void* src, int sz) {
    asm volatile("cp.async.cg.shared.global [%0], [%1], 16, %2;\n"
                 :: "r"(dst), "l"(src), "r"(sz));
}
__device__ __forceinline__ void cp_commit() {
    asm volatile("cp.async.commit_group;\n" ::: "memory");
}
template <int N>
__device__ __forceinline__ void cp_wait() {
    asm volatile("cp.async.wait_group %0;\n" :: "n"(N) : "memory");
}

// ---------------- fused dual-GEMM fp16, 3-stage pipeline + ldmatrix ----------
// out = hself @ Ws^T' + mean @ Wn^T' + b. CTA 128x128, BK=32 halves, 8 chunks.
// RACE FIX vs round 8: final iteration must fully drain cp.async (wait<0>),
// otherwise the last chunk's tiles can be read before they land.
#define STW 20                // words per smem row (stride 80B)
#define STAGE_W (128 * STW)   // words per stage per matrix
template <bool LAYER1>
__global__ void __launch_bounds__(256, 2)
k_gemm_mma(const float* __restrict__ bias, float* __restrict__ out, int M) {
    const __half* __restrict__ ws = g_w16[LAYER1 ? 0 : 2];
    const __half* __restrict__ wn = g_w16[LAYER1 ? 1 : 3];

    extern __shared__ uint32_t smem[];
    uint32_t smem_u32 = (uint32_t)__cvta_generic_to_shared(smem);

    int tid = threadIdx.x;
    int wid = tid >> 5, lane = tid & 31;
    int warp_m = (wid & 1) * 64;
    int warp_n = (wid >> 1) * 32;
    int base = blockIdx.x * 128;
    int qr = lane >> 2, qc = lane & 3;

    int r0 = tid >> 1;                 // staging: rows 0..127, 2 threads/row
    int s0h = (tid & 1) * 16;          // halves 0 or 16

    // ldmatrix lane address offsets (bytes, relative to stage base)
    // A x4 tiles: {m..m+7 @k, m+8..15 @k, m..m+7 @k+8h, m+8..15 @k+8h}
    int a_row_add = ((lane >> 3) & 1) * 8 + (lane & 7);
    int a_col_w   = ((lane >> 4) & 1) * 4;
    uint32_t a_off[4];
#pragma unroll
    for (int mt = 0; mt < 4; mt++)
        a_off[mt] = ((warp_m + mt * 16 + a_row_add) * STW + a_col_w) * 4;
    // B x4 tiles: {n..n+7 @k, n..n+7 @k+8h, n+8..15 @k, n+8..15 @k+8h}
    int b_row_add = ((lane >> 4) & 1) * 8 + (lane & 7);
    int b_col_w   = ((lane >> 3) & 1) * 4;
    uint32_t b_off[2];
#pragma unroll
    for (int j = 0; j < 2; j++)
        b_off[j] = ((warp_n + j * 16 + b_row_add) * STW + b_col_w) * 4;

    float acc[4][4][4];
#pragma unroll
    for (int a = 0; a < 4; a++)
#pragma unroll
        for (int b = 0; b < 4; b++)
#pragma unroll
            for (int c = 0; c < 4; c++) acc[a][b][c] = 0.f;

#define LOAD_CHUNK(c, stage)                                                      \
    {                                                                             \
        int p_ = (c) >> 2, kc_ = ((c) & 3) * 32;                                  \
        const __half* A_ = p_ ? g_mean16 : g_hhalf;                               \
        const __half* W_ = p_ ? wn : ws;                                          \
        uint32_t ab = smem_u32 + (uint32_t)(stage) * STAGE_W * 4;                 \
        uint32_t bb = smem_u32 + (3u + (uint32_t)(stage)) * STAGE_W * 4;          \
        int ok = (base + r0 < M) ? 16 : 0;                                        \
        cp16(ab + (r0 * STW) * 4 + s0h * 2,                                       \
             A_ + (size_t)(base + r0) * F + kc_ + s0h, ok);                       \
        cp16(ab + (r0 * STW) * 4 + (s0h + 8) * 2,                                 \
             A_ + (size_t)(base + r0) * F + kc_ + s0h + 8, ok);                   \
        cp16(bb + (r0 * STW) * 4 + s0h * 2,                                       \
             W_ + (size_t)r0 * F + kc_ + s0h, 16);                                \
        cp16(bb + (r0 * STW) * 4 + (s0h + 8) * 2,                                 \
             W_ + (size_t)r0 * F + kc_ + s0h + 8, 16);                            \
    }

    LOAD_CHUNK(0, 0); cp_commit();
    LOAD_CHUNK(1, 1); cp_commit();

    for (int c = 0; c < 8; ++c) {
        if (c == 7) cp_wait<0>();   // last chunk: FULL drain (race fix)
        else        cp_wait<1>();
        __syncthreads();
        if (c + 2 < 8) {
            LOAD_CHUNK(c + 2, (c + 2) % 3);
            cp_commit();
        }
        int stg = c % 3;
        uint32_t ab = smem_u32 + (uint32_t)stg * STAGE_W * 4;
        uint32_t bb = smem_u32 + (3u + (uint32_t)stg) * STAGE_W * 4;
#pragma unroll
        for (int s = 0; s < 2; s++) {       // two k16 steps per 32-half chunk
            uint32_t kb = s * 32;           // 8 words
            uint32_t bfr[4][2];
            ldsm4(bfr[0][0], bfr[0][1], bfr[1][0], bfr[1][1], bb + b_off[0] + kb);
            ldsm4(bfr[2][0], bfr[2][1], bfr[3][0], bfr[3][1], bb + b_off[1] + kb);
#pragma unroll
            for (int mt = 0; mt < 4; mt++) {
                uint32_t afr[4];
                ldsm4(afr[0], afr[1], afr[2], afr[3], ab + a_off[mt] + kb);
#pragma unroll
                for (int nt = 0; nt < 4; nt++)
                    mma_f16(acc[mt][nt], afr, bfr[nt]);
            }
        }
    }

    // epilogue
#pragma unroll
    for (int nt = 0; nt < 4; nt++) {
        int col = warp_n + nt * 8 + 2 * qc;
        float b0 = bias[col], b1 = bias[col + 1];
#pragma unroll
        for (int mt = 0; mt < 4; mt++) {
#pragma unroll
            for (int h = 0; h < 2; h++) {
                int row = base + warp_m + mt * 16 + qr + h * 8;
                if (row < M) {
                    float v0 = acc[mt][nt][2 * h] + b0;
                    float v1 = acc[mt][nt][2 * h + 1] + b1;
                    if (LAYER1) {
                        v0 = v0 > 0.f ? v0 : 0.2f * v0;
                        v1 = v1 > 0.f ? v1 : 0.2f * v1;
                        __half2 hv = __floats2half2_rn(v0, v1);
                        *(__half2*)(g_hhalf + (size_t)row * F + col) = hv;
                    } else {
                        float2 vv = make_float2(v0, v1);
                        *(float2*)(out + (size_t)row * F + col) = vv;
                    }
                }
            }
        }
    }
#undef LOAD_CHUNK
}

// ---------------- launch ----------------------------------------------------
extern "C" void kernel_launch(void* const* d_in, const int* in_sizes, int n_in,
                              void* d_out, int out_size) {
    const float* emb = (const float*)d_in[0];
    const float* W1s = (const float*)d_in[1];
    const float* W1n = (const float*)d_in[2];
    const float* b1  = (const float*)d_in[3];
    const float* W2s = (const float*)d_in[4];
    const float* W2n = (const float*)d_in[5];
    const float* b2  = (const float*)d_in[6];
    const int*   edg = (const int*)d_in[7];

    int E = in_sizes[7] / 2;
    int M = in_sizes[0] / F;
    const int* src = edg;
    const int* dst = edg + E;
    float* out = (float*)d_out;

    int n = M + 1;
    int scanBlocks = (n + SCAN_TILE - 1) / SCAN_TILE;
    int n4 = M * F / 4;
    int histBlocks = (E + 255) / 256;
    int cvtBlocks = (n4 + 255) / 256;
    int wBlocks = (4 * F * F + 255) / 256;

    const int GEMM_SMEM = 6 * STAGE_W * 4;   // 61440 B
    cudaFuncSetAttribute(k_gemm_mma<true>,
                         cudaFuncAttributeMaxDynamicSharedMemorySize, GEMM_SMEM);
    cudaFuncSetAttribute(k_gemm_mma<false>,
                         cudaFuncAttributeMaxDynamicSharedMemorySize, GEMM_SMEM);

    // zero rowptr via memset node (replaces k_zero launch)
    void* rowptr_ptr = nullptr;
    cudaGetSymbolAddress(&rowptr_ptr, g_rowptr);
    cudaMemsetAsync(rowptr_ptr, 0, (size_t)n * sizeof(int), 0);

    k_prep<<<histBlocks + cvtBlocks + wBlocks, 256>>>(
        emb, W1s, W1n, W2s, W2n, dst, E, n4, histBlocks, cvtBlocks);
    k_scan1<<<scanBlocks, 1024>>>(n);
    k_scan3<<<scanBlocks, 1024>>>(n, scanBlocks);
    k_scatter<<<(E + 255) / 256, 256>>>(src, dst, E);

    int aggBlocks = (M * 32 + 255) / 256;
    int gemmBlocks = (M + 127) / 128;

    // layer 1
    k_agg<<<aggBlocks, 256>>>(M);
    k_gemm_mma<true><<<gemmBlocks, 256, GEMM_SMEM>>>(b1, nullptr, M);

    // layer 2
    k_agg<<<aggBlocks, 256>>>(M);
    k_gemm_mma<false><<<gemmBlocks, 256, GEMM_SMEM>>>(b2, out, M);
}